// round 5
// baseline (speedup 1.0000x reference)
#include <cuda_runtime.h>

// Problem constants
#define Bsz 2
#define Tsz 2048
#define Csz 1024
#define Hn  16
#define Dh  64

// Scratch (allocation-free rule: __device__ globals)
// g_qkv layout: [which(3)][b][h][t][d]
__device__ float g_qkv[3ull * Bsz * Hn * Tsz * Dh];   // 48 MB
// g_y2 layout: [b*T, C] (attention output, pre-projection)
__device__ float g_y2[(size_t)Bsz * Tsz * Csz];       // 16 MB

// ---------------------------------------------------------------------------
// GEMM: C[m,n] = sum_k A[m,k] * W[n,k]   (torch Linear: x @ W^T)
// 128x128 tile, BK=8, 256 threads, 8x8 per thread (split-64 fragments).
// MODE 0: A = x param, scatter into g_qkv.  MODE 1: A = g_y2, C = d_out.
// ---------------------------------------------------------------------------
template<int MODE>
__global__ void __launch_bounds__(256, 2) sgemm_tn(const float* __restrict__ A,
                                                   const float* __restrict__ W,
                                                   float* __restrict__ C,
                                                   int M, int N, int K)
{
    __shared__ float As[8][128];
    __shared__ float Ws[8][128];

    const float* Aeff = (MODE == 1) ? (const float*)g_y2 : A;

    const int tid = threadIdx.x;
    const int m0 = blockIdx.y * 128;
    const int n0 = blockIdx.x * 128;

    const int lr = tid >> 1;          // 0..127 row within tile
    const int lk = (tid & 1) * 4;     // 0 or 4
    const float* Ap = Aeff + (size_t)(m0 + lr) * K + lk;
    const float* Wp = W    + (size_t)(n0 + lr) * K + lk;

    const int tx = tid & 15;
    const int ty = tid >> 4;

    float acc[8][8];
#pragma unroll
    for (int i = 0; i < 8; i++)
#pragma unroll
        for (int j = 0; j < 8; j++) acc[i][j] = 0.f;

    for (int k0 = 0; k0 < K; k0 += 8) {
        float4 av = *(const float4*)(Ap + k0);
        float4 wv = *(const float4*)(Wp + k0);
        As[lk + 0][lr] = av.x; As[lk + 1][lr] = av.y;
        As[lk + 2][lr] = av.z; As[lk + 3][lr] = av.w;
        Ws[lk + 0][lr] = wv.x; Ws[lk + 1][lr] = wv.y;
        Ws[lk + 2][lr] = wv.z; Ws[lk + 3][lr] = wv.w;
        __syncthreads();

#pragma unroll
        for (int kk = 0; kk < 8; kk++) {
            float ra[8], rb[8];
            *(float4*)&ra[0] = *(const float4*)&As[kk][ty * 4];
            *(float4*)&ra[4] = *(const float4*)&As[kk][64 + ty * 4];
            *(float4*)&rb[0] = *(const float4*)&Ws[kk][tx * 4];
            *(float4*)&rb[4] = *(const float4*)&Ws[kk][64 + tx * 4];
#pragma unroll
            for (int i = 0; i < 8; i++)
#pragma unroll
                for (int j = 0; j < 8; j++)
                    acc[i][j] = fmaf(ra[i], rb[j], acc[i][j]);
        }
        __syncthreads();
    }

#pragma unroll
    for (int i = 0; i < 8; i++) {
        const int gm = m0 + ((i < 4) ? (ty * 4 + i) : (64 + ty * 4 + i - 4));
#pragma unroll
        for (int j = 0; j < 8; j++) {
            const int gn = n0 + ((j < 4) ? (tx * 4 + j) : (64 + tx * 4 + j - 4));
            if (MODE == 0) {
                // gm = b*T + t ; gn = which*C + h*D + d
                const int b = gm >> 11, t = gm & (Tsz - 1);
                const int which = gn >> 10, cc = gn & (Csz - 1);
                const int h = cc >> 6, d = cc & 63;
                g_qkv[((((size_t)which * Bsz + b) * Hn + h) * Tsz + t) * Dh + d] = acc[i][j];
            } else {
                C[(size_t)gm * N + gn] = acc[i][j];
            }
        }
    }
}

// ---------------------------------------------------------------------------
// Flash attention (causal). One CTA = 64 queries of one (b,h).
// 256 threads: 16x16 grid, each thread owns 4x4 S and 4x4 O fragments.
// smem tiles row-major with stride 65 -> conflict-free scalar LDS.
// ---------------------------------------------------------------------------
__global__ void __launch_bounds__(256, 2) attn_kernel(float* __restrict__ y2)
{
    __shared__ float Qs[64][65];   // Q[q][d], pre-scaled by 1/sqrt(D)
    __shared__ float KPs[64][65];  // K[k][d], then reused as P[q][k]
    __shared__ float Vs[64][65];   // V[k][d]

    const int qt  = blockIdx.x;          // query tile (64 rows)
    const int h   = blockIdx.y;
    const int b   = blockIdx.z;
    const int tid = threadIdx.x;
    const int tx  = tid & 15;            // col group
    const int ty  = tid >> 4;            // row group

    const size_t hb = ((size_t)b * Hn + h) * (size_t)Tsz * Dh;
    const float* Qg = g_qkv + 0ull * Bsz * Hn * Tsz * Dh + hb;
    const float* Kg = g_qkv + 1ull * Bsz * Hn * Tsz * Dh + hb;
    const float* Vg = g_qkv + 2ull * Bsz * Hn * Tsz * Dh + hb;

    const int q0 = qt * 64;

    // Load Q tile, scaled by 1/8 (1/sqrt(64))
    for (int idx = tid; idx < 64 * 16; idx += 256) {
        const int r = idx >> 4, c4 = (idx & 15) * 4;
        float4 v = *(const float4*)(Qg + (size_t)(q0 + r) * Dh + c4);
        Qs[r][c4 + 0] = v.x * 0.125f;
        Qs[r][c4 + 1] = v.y * 0.125f;
        Qs[r][c4 + 2] = v.z * 0.125f;
        Qs[r][c4 + 3] = v.w * 0.125f;
    }

    float m_i[4], l_i[4], o[4][4];
#pragma unroll
    for (int i = 0; i < 4; i++) {
        m_i[i] = -1e30f; l_i[i] = 0.f;
#pragma unroll
        for (int j = 0; j < 4; j++) o[i][j] = 0.f;
    }

    for (int jt = 0; jt <= qt; jt++) {
        __syncthreads();   // protect Qs (first iter) / KPs,Vs (prev iter reads)
        const int kk0 = jt * 64;
        for (int idx = tid; idx < 64 * 16; idx += 256) {
            const int r = idx >> 4, c4 = (idx & 15) * 4;
            float4 kv = *(const float4*)(Kg + (size_t)(kk0 + r) * Dh + c4);
            KPs[r][c4 + 0] = kv.x; KPs[r][c4 + 1] = kv.y;
            KPs[r][c4 + 2] = kv.z; KPs[r][c4 + 3] = kv.w;
            float4 vv = *(const float4*)(Vg + (size_t)(kk0 + r) * Dh + c4);
            Vs[r][c4 + 0] = vv.x; Vs[r][c4 + 1] = vv.y;
            Vs[r][c4 + 2] = vv.z; Vs[r][c4 + 3] = vv.w;
        }
        __syncthreads();

        // S = Q * K^T  (inner dim = d)
        float s[4][4];
#pragma unroll
        for (int i = 0; i < 4; i++)
#pragma unroll
            for (int j = 0; j < 4; j++) s[i][j] = 0.f;

#pragma unroll 8
        for (int kk = 0; kk < 64; kk++) {
            float rq[4], rk[4];
#pragma unroll
            for (int i = 0; i < 4; i++) rq[i] = Qs[ty * 4 + i][kk];
#pragma unroll
            for (int j = 0; j < 4; j++) rk[j] = KPs[tx * 4 + j][kk];
#pragma unroll
            for (int i = 0; i < 4; i++)
#pragma unroll
                for (int j = 0; j < 4; j++)
                    s[i][j] = fmaf(rq[i], rk[j], s[i][j]);
        }

        // Causal mask (only the diagonal tile can contain masked entries)
        if (jt == qt) {
#pragma unroll
            for (int i = 0; i < 4; i++)
#pragma unroll
                for (int j = 0; j < 4; j++)
                    if (kk0 + tx * 4 + j > q0 + ty * 4 + i) s[i][j] = -1e30f;
        }

        // Online softmax: rows distributed over 16 lanes (same half-warp)
#pragma unroll
        for (int i = 0; i < 4; i++) {
            float rmax = fmaxf(fmaxf(s[i][0], s[i][1]), fmaxf(s[i][2], s[i][3]));
#pragma unroll
            for (int off = 1; off < 16; off <<= 1)
                rmax = fmaxf(rmax, __shfl_xor_sync(0xffffffffu, rmax, off));
            const float mn = fmaxf(m_i[i], rmax);
            const float alpha = __expf(m_i[i] - mn);
            float rs = 0.f;
#pragma unroll
            for (int j = 0; j < 4; j++) {
                s[i][j] = __expf(s[i][j] - mn);
                rs += s[i][j];
            }
#pragma unroll
            for (int off = 1; off < 16; off <<= 1)
                rs += __shfl_xor_sync(0xffffffffu, rs, off);
            l_i[i] = l_i[i] * alpha + rs;
            m_i[i] = mn;
#pragma unroll
            for (int j = 0; j < 4; j++) o[i][j] *= alpha;
        }

        __syncthreads();           // all S reads of KPs done
        // Write P into KPs as P[q][k]
#pragma unroll
        for (int i = 0; i < 4; i++)
#pragma unroll
            for (int j = 0; j < 4; j++)
                KPs[ty * 4 + i][tx * 4 + j] = s[i][j];
        __syncthreads();

        // O += P * V   (inner dim = k)
#pragma unroll 8
        for (int kk = 0; kk < 64; kk++) {
            float rp[4], rv[4];
#pragma unroll
            for (int i = 0; i < 4; i++) rp[i] = KPs[ty * 4 + i][kk];
#pragma unroll
            for (int j = 0; j < 4; j++) rv[j] = Vs[kk][tx * 4 + j];
#pragma unroll
            for (int i = 0; i < 4; i++)
#pragma unroll
                for (int j = 0; j < 4; j++)
                    o[i][j] = fmaf(rp[i], rv[j], o[i][j]);
        }
    }

    // Normalize and write to y2[b*T + t][h*D + d]
#pragma unroll
    for (int i = 0; i < 4; i++) {
        const float inv = 1.f / l_i[i];
        const int t = q0 + ty * 4 + i;
        const size_t row = ((size_t)b * Tsz + t) * Csz + (size_t)h * Dh;
#pragma unroll
        for (int j = 0; j < 4; j++)
            y2[row + tx * 4 + j] = o[i][j] * inv;
    }
}

// ---------------------------------------------------------------------------
extern "C" void kernel_launch(void* const* d_in, const int* in_sizes, int n_in,
                              void* d_out, int out_size)
{
    const float* x      = (const float*)d_in[0];   // [B,T,C]
    const float* w_attn = (const float*)d_in[1];   // [3C,C]
    const float* w_proj = (const float*)d_in[2];   // [C,C]
    // d_in[3] = mask (unused; causal handled analytically)
    float* out = (float*)d_out;                    // [B,T,C]

    const int M = Bsz * Tsz;       // 4096

    // 1) QKV projection -> g_qkv scatter
    {
        dim3 grid((3 * Csz) / 128, M / 128);       // (24, 32)
        sgemm_tn<0><<<grid, 256>>>(x, w_attn, nullptr, M, 3 * Csz, Csz);
    }

    // 2) Causal flash attention -> g_y2
    {
        float* y2;
        cudaGetSymbolAddress((void**)&y2, g_y2);
        dim3 grid(Tsz / 64, Hn, Bsz);              // (32, 16, 2)
        attn_kernel<<<grid, 256>>>(y2);
    }

    // 3) Output projection -> d_out
    {
        dim3 grid(Csz / 128, M / 128);             // (8, 32)
        sgemm_tn<1><<<grid, 256>>>(nullptr, w_proj, out, M, Csz, Csz);
    }
}

// round 8
// speedup vs baseline: 1.4913x; 1.4913x over previous
#include <cuda_runtime.h>
#include <cuda_bf16.h>
#include <cstdint>

// Problem constants
#define Bsz 2
#define Tsz 2048
#define Csz 1024
#define Hn  16
#define Dh  64

// Scratch (allocation-free rule: __device__ globals)
__device__ float g_qkv[3ull * Bsz * Hn * Tsz * Dh];   // [which][b][h][t][d]
__device__ float g_y2[(size_t)Bsz * Tsz * Csz];       // [b*T][C]

// ===========================================================================
// Base-ISA tensor-core helpers (sm_80+; safe for compute_103 PTX target)
// ===========================================================================
__device__ __forceinline__ uint32_t smem_u32(const void* p) {
    uint32_t a;
    asm("{ .reg .u64 t; cvta.to.shared.u64 t, %1; cvt.u32.u64 %0, t; }"
        : "=r"(a) : "l"(p));
    return a;
}
__device__ __forceinline__ void ldm4(uint32_t* r, uint32_t addr) {
    asm volatile("ldmatrix.sync.aligned.m8n8.x4.shared.b16 {%0,%1,%2,%3}, [%4];"
                 : "=r"(r[0]), "=r"(r[1]), "=r"(r[2]), "=r"(r[3]) : "r"(addr));
}
__device__ __forceinline__ void mma_bf16(float* d, const uint32_t* a,
                                         uint32_t b0, uint32_t b1) {
    asm volatile(
        "mma.sync.aligned.m16n8k16.row.col.f32.bf16.bf16.f32 "
        "{%0,%1,%2,%3}, {%4,%5,%6,%7}, {%8,%9}, {%0,%1,%2,%3};"
        : "+f"(d[0]), "+f"(d[1]), "+f"(d[2]), "+f"(d[3])
        : "r"(a[0]), "r"(a[1]), "r"(a[2]), "r"(a[3]), "r"(b0), "r"(b1));
}
// bf16 hi/lo split of 2 floats -> packed bf16x2 words
__device__ __forceinline__ void cvt_pair(float x0, float x1,
                                         uint32_t& h, uint32_t& l) {
    __nv_bfloat162 hb = __floats2bfloat162_rn(x0, x1);
    h = *reinterpret_cast<uint32_t*>(&hb);
    float r0 = x0 - __bfloat162float(hb.x);
    float r1 = x1 - __bfloat162float(hb.y);
    __nv_bfloat162 lb = __floats2bfloat162_rn(r0, r1);
    l = *reinterpret_cast<uint32_t*>(&lb);
}

// ===========================================================================
// Tensor-core GEMM: C[m,n] = sum_k A[m,k]*W[n,k], fp32 in/out, K=1024.
// CTA tile 128x128, K-chunk 32 (fp32), double-buffered smem, 8 warps (64x32).
// bf16 hi/lo compensation: D += Ah*Wh + Ah*Wl + Al*Wh  (rel err ~1e-5).
// smem rows padded to 80B -> conflict-free ldmatrix without swizzle.
// MODE 0: A = x, scatter into g_qkv.  MODE 1: A = g_y2, C = d_out.
// ===========================================================================
#define GK      1024
#define BK      32
#define NCH     (GK / BK)          // 32 chunks
#define RS      80                 // bytes per bf16 row (32 bf16 = 64B + 16B pad)
#define TILE_B  (128 * RS)         // 10240 B per tile
#define BUF_B   (4 * TILE_B)       // Ah, Al, Wh, Wl
#define GEMM_SMEM (2 * BUF_B)      // 81920 B (double buffered)

template<int MODE>
__global__ void __launch_bounds__(256) gemm_tc(const float* __restrict__ A_,
                                               const float* __restrict__ W,
                                               float* __restrict__ C)
{
    extern __shared__ char smc[];
    const float* A = (MODE == 1) ? (const float*)g_y2 : A_;

    const int tid = threadIdx.x;
    const int wid = tid >> 5;
    const int l   = tid & 31;
    const int m0  = blockIdx.y * 128;
    const int n0  = blockIdx.x * 128;
    const int wm  = wid & 1;       // 2 M-warps (64 rows each)
    const int wn  = wid >> 1;      // 4 N-warps (32 cols each)

    // Global-load assignment: float4 f = tid + q*256 ; row = f>>3, c4 = f&7
    const float* ap[4];
    const float* wp[4];
    uint32_t sts_off[4];
#pragma unroll
    for (int q = 0; q < 4; q++) {
        const int f = tid + q * 256;
        const int r = f >> 3, c4 = f & 7;
        ap[q] = A + (size_t)(m0 + r) * GK + c4 * 4;
        wp[q] = W + (size_t)(n0 + r) * GK + c4 * 4;
        sts_off[q] = (uint32_t)(r * RS + c4 * 8);
    }
    const uint32_t sb = smem_u32(smc);

    float4 ra[4], rw[4];
    // Prologue: chunk 0 -> buffer 0
#pragma unroll
    for (int q = 0; q < 4; q++) { ra[q] = *(const float4*)ap[q];
                                  rw[q] = *(const float4*)wp[q]; }
#pragma unroll
    for (int q = 0; q < 4; q++) {
        uint32_t h0, l0, h1, l1;
        char* base = smc + sts_off[q];
        cvt_pair(ra[q].x, ra[q].y, h0, l0); cvt_pair(ra[q].z, ra[q].w, h1, l1);
        *(uint2*)(base)              = make_uint2(h0, h1);
        *(uint2*)(base + TILE_B)     = make_uint2(l0, l1);
        cvt_pair(rw[q].x, rw[q].y, h0, l0); cvt_pair(rw[q].z, rw[q].w, h1, l1);
        *(uint2*)(base + 2 * TILE_B) = make_uint2(h0, h1);
        *(uint2*)(base + 3 * TILE_B) = make_uint2(l0, l1);
    }
    __syncthreads();

    float acc[4][4][4];
#pragma unroll
    for (int i = 0; i < 4; i++)
#pragma unroll
        for (int j = 0; j < 4; j++)
#pragma unroll
            for (int k = 0; k < 4; k++) acc[i][j][k] = 0.f;

    // Precomputed per-lane ldmatrix row/col components
    const int lrow = l & 15;           // row within 16-row block
    const int lku  = l >> 4;           // k-halfstep (16B unit)

    for (int c = 0; c < NCH; c++) {
        // Stage next chunk's globals (overlaps MMA below)
        if (c + 1 < NCH) {
            const int k0 = (c + 1) * BK;
#pragma unroll
            for (int q = 0; q < 4; q++) { ra[q] = *(const float4*)(ap[q] + k0);
                                          rw[q] = *(const float4*)(wp[q] + k0); }
        }

        const uint32_t buf = sb + (uint32_t)(c & 1) * BUF_B;
#pragma unroll
        for (int s = 0; s < 2; s++) {           // two k16 steps per chunk
            uint32_t ah[4][4], al[4][4], bh[2][4], bl[2][4];
            const uint32_t kcol = (uint32_t)(16 * (2 * s + lku));
#pragma unroll
            for (int i = 0; i < 4; i++) {
                uint32_t addr = buf + (uint32_t)((wm * 64 + i * 16 + lrow) * RS) + kcol;
                ldm4(ah[i], addr);
                ldm4(al[i], addr + TILE_B);
            }
#pragma unroll
            for (int jp = 0; jp < 2; jp++) {
                uint32_t addr = buf + 2 * TILE_B
                              + (uint32_t)((wn * 32 + jp * 16 + lrow) * RS) + kcol;
                ldm4(bh[jp], addr);
                ldm4(bl[jp], addr + TILE_B);
            }
#pragma unroll
            for (int i = 0; i < 4; i++)
#pragma unroll
                for (int j = 0; j < 4; j++) {
                    const int jp = j >> 1, p = j & 1;
                    mma_bf16(acc[i][j], ah[i], bh[jp][p], bh[jp][p + 2]);
                    mma_bf16(acc[i][j], ah[i], bl[jp][p], bl[jp][p + 2]);
                    mma_bf16(acc[i][j], al[i], bh[jp][p], bh[jp][p + 2]);
                }
        }

        // STS next chunk into the other buffer (it was fully consumed at c-1)
        if (c + 1 < NCH) {
            char* nb = smc + ((c + 1) & 1) * BUF_B;
#pragma unroll
            for (int q = 0; q < 4; q++) {
                uint32_t h0, l0, h1, l1;
                char* base = nb + sts_off[q];
                cvt_pair(ra[q].x, ra[q].y, h0, l0); cvt_pair(ra[q].z, ra[q].w, h1, l1);
                *(uint2*)(base)              = make_uint2(h0, h1);
                *(uint2*)(base + TILE_B)     = make_uint2(l0, l1);
                cvt_pair(rw[q].x, rw[q].y, h0, l0); cvt_pair(rw[q].z, rw[q].w, h1, l1);
                *(uint2*)(base + 2 * TILE_B) = make_uint2(h0, h1);
                *(uint2*)(base + 3 * TILE_B) = make_uint2(l0, l1);
            }
        }
        __syncthreads();
    }

    // Epilogue: frag (c0,c1) at (row, n..n+1), (c2,c3) at (row+8, n..n+1)
#pragma unroll
    for (int i = 0; i < 4; i++) {
#pragma unroll
        for (int j = 0; j < 4; j++) {
            const int gm0 = m0 + wm * 64 + i * 16 + (l >> 2);
            const int gn  = n0 + wn * 32 + j * 8 + 2 * (l & 3);
#pragma unroll
            for (int half = 0; half < 2; half++) {
                const int gm = gm0 + half * 8;
                float2 v = make_float2(acc[i][j][half * 2], acc[i][j][half * 2 + 1]);
                if (MODE == 0) {
                    const int b = gm >> 11, t = gm & (Tsz - 1);
                    const int which = gn >> 10, cc = gn & (Csz - 1);
                    const int h = cc >> 6, d = cc & 63;
                    *(float2*)&g_qkv[((((size_t)which * Bsz + b) * Hn + h) * Tsz + t) * Dh + d] = v;
                } else {
                    *(float2*)&C[(size_t)gm * Csz + gn] = v;
                }
            }
        }
    }
}

// ===========================================================================
// Flash attention (causal). One CTA = 64 queries of one (b,h). 256 threads,
// 16x16 thread grid, 4x4 fragments. Transposed smem (stride 68) so every
// fragment read is an aligned LDS.128.
// ===========================================================================
__global__ void __launch_bounds__(256, 2) attn_kernel(float* __restrict__ y2)
{
    __shared__ float Qt[64][68];    // Q^T: [d][q], pre-scaled by 1/sqrt(D)
    __shared__ float KPt[64][68];   // K^T: [d][k]; reused as P^T: [k][q]
    __shared__ float Vs[64][68];    // V:   [k][d]

    const int qt  = blockIdx.x;
    const int h   = blockIdx.y;
    const int b   = blockIdx.z;
    const int tid = threadIdx.x;
    const int tx  = tid & 15;
    const int ty  = tid >> 4;

    const size_t hb = ((size_t)b * Hn + h) * (size_t)Tsz * Dh;
    const float* Qg = g_qkv + 0ull * Bsz * Hn * Tsz * Dh + hb;
    const float* Kg = g_qkv + 1ull * Bsz * Hn * Tsz * Dh + hb;
    const float* Vg = g_qkv + 2ull * Bsz * Hn * Tsz * Dh + hb;

    const int q0 = qt * 64;

    // Load Q transposed, scaled by 1/8
    for (int idx = tid; idx < 64 * 16; idx += 256) {
        const int r = idx >> 4, c4 = (idx & 15) * 4;
        float4 v = *(const float4*)(Qg + (size_t)(q0 + r) * Dh + c4);
        Qt[c4 + 0][r] = v.x * 0.125f;
        Qt[c4 + 1][r] = v.y * 0.125f;
        Qt[c4 + 2][r] = v.z * 0.125f;
        Qt[c4 + 3][r] = v.w * 0.125f;
    }

    float m_i[4], l_i[4], o[4][4];
#pragma unroll
    for (int i = 0; i < 4; i++) {
        m_i[i] = -1e30f; l_i[i] = 0.f;
#pragma unroll
        for (int j = 0; j < 4; j++) o[i][j] = 0.f;
    }

    for (int jt = 0; jt <= qt; jt++) {
        __syncthreads();     // Qt ready (1st iter) / prev PV reads done
        const int kk0 = jt * 64;
        for (int idx = tid; idx < 64 * 16; idx += 256) {
            const int r = idx >> 4, c4 = (idx & 15) * 4;
            float4 kv = *(const float4*)(Kg + (size_t)(kk0 + r) * Dh + c4);
            KPt[c4 + 0][r] = kv.x; KPt[c4 + 1][r] = kv.y;
            KPt[c4 + 2][r] = kv.z; KPt[c4 + 3][r] = kv.w;
            float4 vv = *(const float4*)(Vg + (size_t)(kk0 + r) * Dh + c4);
            *(float4*)&Vs[r][c4] = vv;
        }
        __syncthreads();

        // S = Q*K^T (inner dim d): vectorized LDS.128 fragment reads
        float s[4][4];
#pragma unroll
        for (int i = 0; i < 4; i++)
#pragma unroll
            for (int j = 0; j < 4; j++) s[i][j] = 0.f;

#pragma unroll 8
        for (int kk = 0; kk < 64; kk++) {
            float4 rq = *(const float4*)&Qt[kk][ty * 4];
            float4 rk = *(const float4*)&KPt[kk][tx * 4];
            const float* q = &rq.x;
            const float* k = &rk.x;
#pragma unroll
            for (int i = 0; i < 4; i++)
#pragma unroll
                for (int j = 0; j < 4; j++)
                    s[i][j] = fmaf(q[i], k[j], s[i][j]);
        }

        if (jt == qt) {
#pragma unroll
            for (int i = 0; i < 4; i++)
#pragma unroll
                for (int j = 0; j < 4; j++)
                    if (kk0 + tx * 4 + j > q0 + ty * 4 + i) s[i][j] = -1e30f;
        }

        // Online softmax (rows spread over 16 lanes of the same half-warp)
#pragma unroll
        for (int i = 0; i < 4; i++) {
            float rmax = fmaxf(fmaxf(s[i][0], s[i][1]), fmaxf(s[i][2], s[i][3]));
#pragma unroll
            for (int off = 1; off < 16; off <<= 1)
                rmax = fmaxf(rmax, __shfl_xor_sync(0xffffffffu, rmax, off));
            const float mn = fmaxf(m_i[i], rmax);
            const float alpha = __expf(m_i[i] - mn);
            float rs = 0.f;
#pragma unroll
            for (int j = 0; j < 4; j++) {
                s[i][j] = __expf(s[i][j] - mn);
                rs += s[i][j];
            }
#pragma unroll
            for (int off = 1; off < 16; off <<= 1)
                rs += __shfl_xor_sync(0xffffffffu, rs, off);
            l_i[i] = l_i[i] * alpha + rs;
            m_i[i] = mn;
#pragma unroll
            for (int j = 0; j < 4; j++) o[i][j] *= alpha;
        }

        __syncthreads();                 // S reads of KPt complete
        // Write P transposed: Pt[k][q]
#pragma unroll
        for (int j = 0; j < 4; j++)
            *(float4*)&KPt[tx * 4 + j][ty * 4] =
                make_float4(s[0][j], s[1][j], s[2][j], s[3][j]);
        __syncthreads();

        // O += P*V (inner dim k): vectorized fragment reads
#pragma unroll 8
        for (int kk = 0; kk < 64; kk++) {
            float4 rp = *(const float4*)&KPt[kk][ty * 4];
            float4 rv = *(const float4*)&Vs[kk][tx * 4];
            const float* p = &rp.x;
            const float* v = &rv.x;
#pragma unroll
            for (int i = 0; i < 4; i++)
#pragma unroll
                for (int j = 0; j < 4; j++)
                    o[i][j] = fmaf(p[i], v[j], o[i][j]);
        }
    }

    // Normalize and write to y2[b*T + t][h*D + d]
#pragma unroll
    for (int i = 0; i < 4; i++) {
        const float inv = 1.f / l_i[i];
        const int t = q0 + ty * 4 + i;
        const size_t row = ((size_t)b * Tsz + t) * Csz + (size_t)h * Dh;
        *(float4*)&y2[row + tx * 4] = make_float4(o[i][0] * inv, o[i][1] * inv,
                                                  o[i][2] * inv, o[i][3] * inv);
    }
}

// ===========================================================================
extern "C" void kernel_launch(void* const* d_in, const int* in_sizes, int n_in,
                              void* d_out, int out_size)
{
    const float* x      = (const float*)d_in[0];   // [B,T,C]
    const float* w_attn = (const float*)d_in[1];   // [3C,C]
    const float* w_proj = (const float*)d_in[2];   // [C,C]
    float* out = (float*)d_out;                    // [B,T,C]

    cudaFuncSetAttribute(gemm_tc<0>, cudaFuncAttributeMaxDynamicSharedMemorySize, GEMM_SMEM);
    cudaFuncSetAttribute(gemm_tc<1>, cudaFuncAttributeMaxDynamicSharedMemorySize, GEMM_SMEM);

    // 1) QKV projection (mma.sync bf16 x3) -> g_qkv scatter
    {
        dim3 grid((3 * Csz) / 128, (Bsz * Tsz) / 128);   // (24, 32)
        gemm_tc<0><<<grid, 256, GEMM_SMEM>>>(x, w_attn, nullptr);
    }

    // 2) Causal flash attention -> g_y2
    {
        float* y2;
        cudaGetSymbolAddress((void**)&y2, g_y2);
        dim3 grid(Tsz / 64, Hn, Bsz);                    // (32, 16, 2)
        attn_kernel<<<grid, 256>>>(y2);
    }

    // 3) Output projection (mma.sync bf16 x3) -> d_out
    {
        dim3 grid(Csz / 128, (Bsz * Tsz) / 128);         // (8, 32)
        gemm_tc<1><<<grid, 256, GEMM_SMEM>>>(nullptr, w_proj, out);
    }
}

// round 9
// speedup vs baseline: 2.3121x; 1.5504x over previous
#include <cuda_runtime.h>
#include <cuda_bf16.h>
#include <cstdint>

// Problem constants
#define Bsz 2
#define Tsz 2048
#define Csz 1024
#define Hn  16
#define Dh  64
#define GK  1024

typedef __nv_bfloat16 bf16;

// ---------------------------------------------------------------------------
// Scratch (__device__ globals; no allocation allowed)
// ---------------------------------------------------------------------------
__device__ bf16 g_xh[(size_t)4096 * 1024], g_xl[(size_t)4096 * 1024];
__device__ bf16 g_wah[(size_t)3072 * 1024], g_wal[(size_t)3072 * 1024];
__device__ bf16 g_wph[(size_t)1024 * 1024], g_wpl[(size_t)1024 * 1024];
// Q,K: [b][h][t][d] ; V stored transposed: [b][h][d][t]
__device__ bf16 g_qh[(size_t)32 * 2048 * 64], g_ql[(size_t)32 * 2048 * 64];
__device__ bf16 g_kh[(size_t)32 * 2048 * 64], g_kl[(size_t)32 * 2048 * 64];
__device__ bf16 g_vth[(size_t)32 * 2048 * 64], g_vtl[(size_t)32 * 2048 * 64];
// attention output (pre-projection), bf16 hi/lo: [b*T][C]
__device__ bf16 g_y2h[(size_t)4096 * 1024], g_y2l[(size_t)4096 * 1024];

// ---------------------------------------------------------------------------
// Base-ISA tensor-core helpers (compile clean for compute_103 base target)
// ---------------------------------------------------------------------------
__device__ __forceinline__ uint32_t smem_u32(const void* p) {
    uint32_t a;
    asm("{ .reg .u64 t; cvta.to.shared.u64 t, %1; cvt.u32.u64 %0, t; }"
        : "=r"(a) : "l"(p));
    return a;
}
__device__ __forceinline__ void ldm4(uint32_t* r, uint32_t addr) {
    asm volatile("ldmatrix.sync.aligned.m8n8.x4.shared.b16 {%0,%1,%2,%3}, [%4];"
                 : "=r"(r[0]), "=r"(r[1]), "=r"(r[2]), "=r"(r[3]) : "r"(addr));
}
__device__ __forceinline__ void mma_bf16(float* d, const uint32_t* a,
                                         uint32_t b0, uint32_t b1) {
    asm volatile(
        "mma.sync.aligned.m16n8k16.row.col.f32.bf16.bf16.f32 "
        "{%0,%1,%2,%3}, {%4,%5,%6,%7}, {%8,%9}, {%0,%1,%2,%3};"
        : "+f"(d[0]), "+f"(d[1]), "+f"(d[2]), "+f"(d[3])
        : "r"(a[0]), "r"(a[1]), "r"(a[2]), "r"(a[3]), "r"(b0), "r"(b1));
}
// fp32 pair -> packed bf16x2 hi + packed bf16x2 residual(lo)
__device__ __forceinline__ void cvt_pair(float x0, float x1,
                                         uint32_t& h, uint32_t& l) {
    __nv_bfloat162 hb = __floats2bfloat162_rn(x0, x1);
    h = *reinterpret_cast<uint32_t*>(&hb);
    float r0 = x0 - __bfloat162float(hb.x);
    float r1 = x1 - __bfloat162float(hb.y);
    __nv_bfloat162 lb = __floats2bfloat162_rn(r0, r1);
    l = *reinterpret_cast<uint32_t*>(&lb);
}

// ---------------------------------------------------------------------------
// One-shot fp32 -> bf16 hi/lo split (grid-stride over float2)
// ---------------------------------------------------------------------------
__global__ void cvt_split(const float* __restrict__ s, bf16* __restrict__ h,
                          bf16* __restrict__ lo, int n2)
{
    int i = blockIdx.x * blockDim.x + threadIdx.x;
    if (i < n2) {
        float2 v = ((const float2*)s)[i];
        uint32_t hh, ll;
        cvt_pair(v.x, v.y, hh, ll);
        ((uint32_t*)h)[i] = hh;
        ((uint32_t*)lo)[i] = ll;
    }
}

// ===========================================================================
// Tensor-core GEMM on pre-split bf16 hi/lo inputs.
// C[m,n] = sum_k A[m,k]*W[n,k]; CTA tile 128x128, K-chunk 32, double-buffered.
// D += Ah*Wh + Ah*Wl + Al*Wh (3-term compensation).
// MODE 0: epilogue -> g_q/g_k (bf16 h/l, [b][h][t][d], Q pre-scaled 1/8)
//                     and g_vt (bf16 h/l, [b][h][d][t]).
// MODE 1: epilogue -> C fp32 [4096][1024].
// ===========================================================================
#define BK      32
#define NCH     (GK / BK)
#define RS      80                 // 32 bf16 = 64B + 16B pad
#define TILE_B  (128 * RS)         // 10240
#define BUF_B   (4 * TILE_B)       // 40960
#define GEMM_SMEM (2 * BUF_B)      // 81920

template<int MODE>
__global__ void __launch_bounds__(256) gemm_tc(const bf16* __restrict__ Ah,
                                               const bf16* __restrict__ Al,
                                               const bf16* __restrict__ Wh,
                                               const bf16* __restrict__ Wl,
                                               float* __restrict__ C)
{
    extern __shared__ char smc[];

    const int tid = threadIdx.x;
    const int wid = tid >> 5;
    const int l   = tid & 31;
    const int m0  = blockIdx.y * 128;
    const int n0  = blockIdx.x * 128;
    const int wm  = wid & 1;
    const int wn  = wid >> 1;

    // 8 LDG slots/thread: f = tid + q*256; tile = f>>9 (Ah,Al,Wh,Wl); r,u within
    const bf16* src[8];
    uint32_t soff[8];
    {
        const bf16* tp[4] = {Ah, Al, Wh, Wl};
#pragma unroll
        for (int q = 0; q < 8; q++) {
            const int f = tid + q * 256;
            const int tile = f >> 9, g = f & 511;
            const int r = g >> 2, u = g & 3;
            const int row = ((tile < 2) ? m0 : n0) + r;
            src[q]  = tp[tile] + (size_t)row * GK + u * 8;
            soff[q] = (uint32_t)(tile * TILE_B + r * RS + u * 16);
        }
    }
    const uint32_t sb = smem_u32(smc);

    // Prologue: chunk 0 -> buffer 0
    uint4 stg[8];
#pragma unroll
    for (int q = 0; q < 8; q++) stg[q] = *(const uint4*)src[q];
#pragma unroll
    for (int q = 0; q < 8; q++) *(uint4*)(smc + soff[q]) = stg[q];
    __syncthreads();

    float acc[4][4][4];
#pragma unroll
    for (int i = 0; i < 4; i++)
#pragma unroll
        for (int j = 0; j < 4; j++)
#pragma unroll
            for (int k = 0; k < 4; k++) acc[i][j][k] = 0.f;

    const int lrow = l & 15;
    const int lku  = l >> 4;

    for (int c = 0; c < NCH; c++) {
        if (c + 1 < NCH) {
            const int k0 = (c + 1) * BK;
#pragma unroll
            for (int q = 0; q < 8; q++) stg[q] = *(const uint4*)(src[q] + k0);
        }

        const uint32_t buf = sb + (uint32_t)(c & 1) * BUF_B;
#pragma unroll
        for (int s = 0; s < 2; s++) {
            uint32_t ah[4][4], al[4][4], bh[2][4], bl[2][4];
            const uint32_t kcol = (uint32_t)(16 * (2 * s + lku));
#pragma unroll
            for (int i = 0; i < 4; i++) {
                uint32_t addr = buf + (uint32_t)((wm * 64 + i * 16 + lrow) * RS) + kcol;
                ldm4(ah[i], addr);
                ldm4(al[i], addr + TILE_B);
            }
#pragma unroll
            for (int jp = 0; jp < 2; jp++) {
                uint32_t addr = buf + 2 * TILE_B
                              + (uint32_t)((wn * 32 + jp * 16 + lrow) * RS) + kcol;
                ldm4(bh[jp], addr);
                ldm4(bl[jp], addr + TILE_B);
            }
#pragma unroll
            for (int i = 0; i < 4; i++)
#pragma unroll
                for (int j = 0; j < 4; j++) {
                    const int jp = j >> 1, p = j & 1;
                    mma_bf16(acc[i][j], ah[i], bh[jp][p], bh[jp][p + 2]);
                    mma_bf16(acc[i][j], ah[i], bl[jp][p], bl[jp][p + 2]);
                    mma_bf16(acc[i][j], al[i], bh[jp][p], bh[jp][p + 2]);
                }
        }

        if (c + 1 < NCH) {
            char* nb = smc + ((c + 1) & 1) * BUF_B;
#pragma unroll
            for (int q = 0; q < 8; q++) *(uint4*)(nb + soff[q]) = stg[q];
        }
        __syncthreads();
    }

    // Epilogue
#pragma unroll
    for (int i = 0; i < 4; i++) {
#pragma unroll
        for (int j = 0; j < 4; j++) {
            const int gm0 = m0 + wm * 64 + i * 16 + (l >> 2);
            const int gn  = n0 + wn * 32 + j * 8 + 2 * (l & 3);
#pragma unroll
            for (int half = 0; half < 2; half++) {
                const int gm = gm0 + half * 8;
                float vx = acc[i][j][half * 2], vy = acc[i][j][half * 2 + 1];
                if (MODE == 1) {
                    *(float2*)&C[(size_t)gm * Csz + gn] = make_float2(vx, vy);
                } else {
                    const int b = gm >> 11, t = gm & (Tsz - 1);
                    const int which = gn >> 10, cc = gn & (Csz - 1);
                    const int h = cc >> 6, d = cc & 63;
                    if (which == 0) { vx *= 0.125f; vy *= 0.125f; }  // 1/sqrt(D)
                    uint32_t hh, ll;
                    cvt_pair(vx, vy, hh, ll);
                    const size_t bh_ = (size_t)b * Hn + h;
                    if (which == 0) {
                        *(uint32_t*)&g_qh[(bh_ * Tsz + t) * Dh + d] = hh;
                        *(uint32_t*)&g_ql[(bh_ * Tsz + t) * Dh + d] = ll;
                    } else if (which == 1) {
                        *(uint32_t*)&g_kh[(bh_ * Tsz + t) * Dh + d] = hh;
                        *(uint32_t*)&g_kl[(bh_ * Tsz + t) * Dh + d] = ll;
                    } else {  // V transposed: [b][h][d][t]
                        __nv_bfloat162 hv = *reinterpret_cast<__nv_bfloat162*>(&hh);
                        __nv_bfloat162 lv = *reinterpret_cast<__nv_bfloat162*>(&ll);
                        g_vth[(bh_ * Dh + d)     * Tsz + t] = hv.x;
                        g_vth[(bh_ * Dh + d + 1) * Tsz + t] = hv.y;
                        g_vtl[(bh_ * Dh + d)     * Tsz + t] = lv.x;
                        g_vtl[(bh_ * Dh + d + 1) * Tsz + t] = lv.y;
                    }
                }
            }
        }
    }
}

// ===========================================================================
// Tensor-core causal flash attention.
// CTA = 64 queries of one (b,h); 128 threads / 4 warps (warp = 16 query rows).
// S = QhKh+QhKl+QlKh (Q frags register-resident), online softmax in frags,
// P repacked from S frags as A operand, O += PhVh+PlVh+PhVl vs smem V^T.
// Output: bf16 hi/lo into g_y2h/g_y2l.
// ===========================================================================
#define ARS   144                 // 64 bf16 = 128B + 16B pad
#define AT_B  (64 * ARS)          // 9216
#define AQ_H  0
#define AQ_L  (AT_B)
#define AK_H  (2 * AT_B)
#define AK_L  (3 * AT_B)
#define AV_H  (4 * AT_B)
#define AV_L  (5 * AT_B)
#define ATTN_SMEM (6 * AT_B)      // 55296

__global__ void __launch_bounds__(128) attn_tc()
{
    extern __shared__ char sma[];
    const uint32_t sb = smem_u32(sma);

    const int qt  = blockIdx.x;
    const int h   = blockIdx.y;
    const int b   = blockIdx.z;
    const int tid = threadIdx.x;
    const int w   = tid >> 5;
    const int l   = tid & 31;
    const int lrow = l & 15;
    const int lku  = l >> 4;
    const int q0   = qt * 64;

    const size_t bh_  = (size_t)b * Hn + h;
    const bf16* qhG  = g_qh  + (bh_ * Tsz + q0) * Dh;
    const bf16* qlG  = g_ql  + (bh_ * Tsz + q0) * Dh;
    const bf16* khG  = g_kh  + bh_ * Tsz * Dh;
    const bf16* klG  = g_kl  + bh_ * Tsz * Dh;
    const bf16* vthG = g_vth + bh_ * Dh * Tsz;
    const bf16* vtlG = g_vtl + bh_ * Dh * Tsz;

    // ---- Load Q tile into smem, then into register fragments ----
    for (int idx = tid; idx < 512; idx += 128) {
        const int r = idx >> 3, u = idx & 7;
        *(uint4*)(sma + AQ_H + r * ARS + u * 16) = *(const uint4*)(qhG + r * Dh + u * 8);
        *(uint4*)(sma + AQ_L + r * ARS + u * 16) = *(const uint4*)(qlG + r * Dh + u * 8);
    }
    __syncthreads();

    uint32_t qh[4][4], ql[4][4];
#pragma unroll
    for (int ks = 0; ks < 4; ks++) {
        const uint32_t addr = sb + (uint32_t)((16 * w + lrow) * ARS + ks * 32 + lku * 16);
        ldm4(qh[ks], addr + AQ_H);
        ldm4(ql[ks], addr + AQ_L);
    }

    // Online-softmax state (2 rows/thread: r=l>>2 and r+8 within warp's m16)
    float m0v = -1e30f, m1v = -1e30f, l0v = 0.f, l1v = 0.f;
    float o[8][4];
#pragma unroll
    for (int j = 0; j < 8; j++)
#pragma unroll
        for (int k = 0; k < 4; k++) o[j][k] = 0.f;

    for (int jt = 0; jt <= qt; jt++) {
        const int kk0 = jt * 64;
        __syncthreads();   // protect prev-iter V reads (and Q smem reads, iter 0)
        for (int idx = tid; idx < 512; idx += 128) {
            const int r = idx >> 3, u = idx & 7;
            *(uint4*)(sma + AK_H + r * ARS + u * 16) =
                *(const uint4*)(khG + (size_t)(kk0 + r) * Dh + u * 8);
            *(uint4*)(sma + AK_L + r * ARS + u * 16) =
                *(const uint4*)(klG + (size_t)(kk0 + r) * Dh + u * 8);
            *(uint4*)(sma + AV_H + r * ARS + u * 16) =
                *(const uint4*)(vthG + (size_t)r * Tsz + kk0 + u * 8);
            *(uint4*)(sma + AV_L + r * ARS + u * 16) =
                *(const uint4*)(vtlG + (size_t)r * Tsz + kk0 + u * 8);
        }
        __syncthreads();

        // ---- S = Q K^T (hi/lo 3-term) ----
        float s[8][4];
#pragma unroll
        for (int j = 0; j < 8; j++)
#pragma unroll
            for (int k = 0; k < 4; k++) s[j][k] = 0.f;

#pragma unroll
        for (int ks = 0; ks < 4; ks++) {
            uint32_t kh[4][4], kl[4][4];
            const uint32_t kc = (uint32_t)(ks * 32 + lku * 16);
#pragma unroll
            for (int jp = 0; jp < 4; jp++) {
                const uint32_t addr = sb + (uint32_t)((16 * jp + lrow) * ARS) + kc;
                ldm4(kh[jp], addr + AK_H);
                ldm4(kl[jp], addr + AK_L);
            }
#pragma unroll
            for (int j = 0; j < 8; j++) {
                const int jp = j >> 1, p = j & 1;
                mma_bf16(s[j], qh[ks], kh[jp][p], kh[jp][p + 2]);
                mma_bf16(s[j], qh[ks], kl[jp][p], kl[jp][p + 2]);
                mma_bf16(s[j], ql[ks], kh[jp][p], kh[jp][p + 2]);
            }
        }

        // ---- Causal mask (diagonal tile only; kk0 == q0 there) ----
        if (jt == qt) {
            const int row0 = 16 * w + (l >> 2);
#pragma unroll
            for (int j = 0; j < 8; j++) {
                const int col = j * 8 + 2 * (l & 3);
                if (col     > row0)     s[j][0] = -1e30f;
                if (col + 1 > row0)     s[j][1] = -1e30f;
                if (col     > row0 + 8) s[j][2] = -1e30f;
                if (col + 1 > row0 + 8) s[j][3] = -1e30f;
            }
        }

        // ---- Online softmax (row = 4 consecutive lanes) ----
        float mx0 = -1e30f, mx1 = -1e30f;
#pragma unroll
        for (int j = 0; j < 8; j++) {
            mx0 = fmaxf(mx0, fmaxf(s[j][0], s[j][1]));
            mx1 = fmaxf(mx1, fmaxf(s[j][2], s[j][3]));
        }
        mx0 = fmaxf(mx0, __shfl_xor_sync(0xffffffffu, mx0, 1));
        mx0 = fmaxf(mx0, __shfl_xor_sync(0xffffffffu, mx0, 2));
        mx1 = fmaxf(mx1, __shfl_xor_sync(0xffffffffu, mx1, 1));
        mx1 = fmaxf(mx1, __shfl_xor_sync(0xffffffffu, mx1, 2));

        const float nm0 = fmaxf(m0v, mx0), nm1 = fmaxf(m1v, mx1);
        const float a0 = __expf(m0v - nm0), a1 = __expf(m1v - nm1);
        float rs0 = 0.f, rs1 = 0.f;
#pragma unroll
        for (int j = 0; j < 8; j++) {
            s[j][0] = __expf(s[j][0] - nm0); rs0 += s[j][0];
            s[j][1] = __expf(s[j][1] - nm0); rs0 += s[j][1];
            s[j][2] = __expf(s[j][2] - nm1); rs1 += s[j][2];
            s[j][3] = __expf(s[j][3] - nm1); rs1 += s[j][3];
        }
        rs0 += __shfl_xor_sync(0xffffffffu, rs0, 1);
        rs0 += __shfl_xor_sync(0xffffffffu, rs0, 2);
        rs1 += __shfl_xor_sync(0xffffffffu, rs1, 1);
        rs1 += __shfl_xor_sync(0xffffffffu, rs1, 2);
        l0v = l0v * a0 + rs0; m0v = nm0;
        l1v = l1v * a1 + rs1; m1v = nm1;
#pragma unroll
        for (int j = 0; j < 8; j++) {
            o[j][0] *= a0; o[j][1] *= a0;
            o[j][2] *= a1; o[j][3] *= a1;
        }

        // ---- P frags directly from S frags (hi/lo), then O += P V ----
#pragma unroll
        for (int kt = 0; kt < 4; kt++) {
            uint32_t ph[4], pl[4];
            cvt_pair(s[2 * kt][0],     s[2 * kt][1],     ph[0], pl[0]);
            cvt_pair(s[2 * kt][2],     s[2 * kt][3],     ph[1], pl[1]);
            cvt_pair(s[2 * kt + 1][0], s[2 * kt + 1][1], ph[2], pl[2]);
            cvt_pair(s[2 * kt + 1][2], s[2 * kt + 1][3], ph[3], pl[3]);

            uint32_t vh[4][4], vl[4][4];
            const uint32_t kc = (uint32_t)(kt * 32 + lku * 16);
#pragma unroll
            for (int dp = 0; dp < 4; dp++) {
                const uint32_t addr = sb + (uint32_t)((16 * dp + lrow) * ARS) + kc;
                ldm4(vh[dp], addr + AV_H);
                ldm4(vl[dp], addr + AV_L);
            }
#pragma unroll
            for (int jd = 0; jd < 8; jd++) {
                const int dp = jd >> 1, p = jd & 1;
                mma_bf16(o[jd], ph, vh[dp][p], vh[dp][p + 2]);
                mma_bf16(o[jd], pl, vh[dp][p], vh[dp][p + 2]);
                mma_bf16(o[jd], ph, vl[dp][p], vl[dp][p + 2]);
            }
        }
    }

    // ---- Normalize + write y2 as bf16 hi/lo ----
    const float inv0 = 1.f / l0v, inv1 = 1.f / l1v;
    const int r0g = q0 + 16 * w + (l >> 2);
#pragma unroll
    for (int jd = 0; jd < 8; jd++) {
        const int col = h * Dh + jd * 8 + 2 * (l & 3);
        uint32_t hh, ll;
        cvt_pair(o[jd][0] * inv0, o[jd][1] * inv0, hh, ll);
        *(uint32_t*)&g_y2h[((size_t)b * Tsz + r0g) * Csz + col] = hh;
        *(uint32_t*)&g_y2l[((size_t)b * Tsz + r0g) * Csz + col] = ll;
        cvt_pair(o[jd][2] * inv1, o[jd][3] * inv1, hh, ll);
        *(uint32_t*)&g_y2h[((size_t)b * Tsz + r0g + 8) * Csz + col] = hh;
        *(uint32_t*)&g_y2l[((size_t)b * Tsz + r0g + 8) * Csz + col] = ll;
    }
}

// ===========================================================================
extern "C" void kernel_launch(void* const* d_in, const int* in_sizes, int n_in,
                              void* d_out, int out_size)
{
    const float* x      = (const float*)d_in[0];   // [B,T,C]
    const float* w_attn = (const float*)d_in[1];   // [3C,C]
    const float* w_proj = (const float*)d_in[2];   // [C,C]
    float* out = (float*)d_out;                    // [B,T,C]

    cudaFuncSetAttribute(gemm_tc<0>, cudaFuncAttributeMaxDynamicSharedMemorySize, GEMM_SMEM);
    cudaFuncSetAttribute(gemm_tc<1>, cudaFuncAttributeMaxDynamicSharedMemorySize, GEMM_SMEM);
    cudaFuncSetAttribute(attn_tc,    cudaFuncAttributeMaxDynamicSharedMemorySize, ATTN_SMEM);

    bf16 *xh, *xl, *wah, *wal, *wph, *wpl, *y2h, *y2l;
    cudaGetSymbolAddress((void**)&xh,  g_xh);  cudaGetSymbolAddress((void**)&xl,  g_xl);
    cudaGetSymbolAddress((void**)&wah, g_wah); cudaGetSymbolAddress((void**)&wal, g_wal);
    cudaGetSymbolAddress((void**)&wph, g_wph); cudaGetSymbolAddress((void**)&wpl, g_wpl);
    cudaGetSymbolAddress((void**)&y2h, g_y2h); cudaGetSymbolAddress((void**)&y2l, g_y2l);

    // 0) One-shot fp32 -> bf16 hi/lo splits
    {
        int n2;
        n2 = 4096 * 1024 / 2;
        cvt_split<<<(n2 + 255) / 256, 256>>>(x, xh, xl, n2);
        n2 = 3072 * 1024 / 2;
        cvt_split<<<(n2 + 255) / 256, 256>>>(w_attn, wah, wal, n2);
        n2 = 1024 * 1024 / 2;
        cvt_split<<<(n2 + 255) / 256, 256>>>(w_proj, wph, wpl, n2);
    }

    // 1) QKV projection -> Q/K ([b][h][t][d]) + V^T ([b][h][d][t]) bf16 h/l
    {
        dim3 grid((3 * Csz) / 128, (Bsz * Tsz) / 128);   // (24, 32)
        gemm_tc<0><<<grid, 256, GEMM_SMEM>>>(xh, xl, wah, wal, nullptr);
    }

    // 2) Tensor-core causal flash attention -> g_y2 (bf16 h/l)
    {
        dim3 grid(Tsz / 64, Hn, Bsz);                    // (32, 16, 2)
        attn_tc<<<grid, 128, ATTN_SMEM>>>();
    }

    // 3) Output projection -> d_out (fp32)
    {
        dim3 grid(Csz / 128, (Bsz * Tsz) / 128);         // (8, 32)
        gemm_tc<1><<<grid, 256, GEMM_SMEM>>>(y2h, y2l, wph, wpl, out);
    }
}

// round 11
// speedup vs baseline: 2.4287x; 1.0504x over previous
#include <cuda_runtime.h>
#include <cuda_bf16.h>
#include <cstdint>

// Problem constants
#define Bsz 2
#define Tsz 2048
#define Csz 1024
#define Hn  16
#define Dh  64
#define GK  1024

typedef __nv_bfloat16 bf16;

// ---------------------------------------------------------------------------
// Scratch (__device__ globals; no allocation allowed)
// ---------------------------------------------------------------------------
__device__ bf16 g_xh[(size_t)4096 * 1024], g_xl[(size_t)4096 * 1024];
__device__ bf16 g_wah[(size_t)3072 * 1024], g_wal[(size_t)3072 * 1024];
__device__ bf16 g_wph[(size_t)1024 * 1024], g_wpl[(size_t)1024 * 1024];
// Q,K: [b][h][t][d] ; V stored transposed: [b][h][d][t]
__device__ bf16 g_qh[(size_t)32 * 2048 * 64], g_ql[(size_t)32 * 2048 * 64];
__device__ bf16 g_kh[(size_t)32 * 2048 * 64], g_kl[(size_t)32 * 2048 * 64];
__device__ bf16 g_vth[(size_t)32 * 2048 * 64], g_vtl[(size_t)32 * 2048 * 64];
// attention output (pre-projection), bf16 hi/lo: [b*T][C]
__device__ bf16 g_y2h[(size_t)4096 * 1024], g_y2l[(size_t)4096 * 1024];

// ---------------------------------------------------------------------------
// Base-ISA helpers (compile clean for compute_103 base target)
// ---------------------------------------------------------------------------
__device__ __forceinline__ uint32_t smem_u32(const void* p) {
    uint32_t a;
    asm("{ .reg .u64 t; cvta.to.shared.u64 t, %1; cvt.u32.u64 %0, t; }"
        : "=r"(a) : "l"(p));
    return a;
}
__device__ __forceinline__ void ldm4(uint32_t* r, uint32_t addr) {
    asm volatile("ldmatrix.sync.aligned.m8n8.x4.shared.b16 {%0,%1,%2,%3}, [%4];"
                 : "=r"(r[0]), "=r"(r[1]), "=r"(r[2]), "=r"(r[3]) : "r"(addr));
}
__device__ __forceinline__ void mma_bf16(float* d, const uint32_t* a,
                                         uint32_t b0, uint32_t b1) {
    asm volatile(
        "mma.sync.aligned.m16n8k16.row.col.f32.bf16.bf16.f32 "
        "{%0,%1,%2,%3}, {%4,%5,%6,%7}, {%8,%9}, {%0,%1,%2,%3};"
        : "+f"(d[0]), "+f"(d[1]), "+f"(d[2]), "+f"(d[3])
        : "r"(a[0]), "r"(a[1]), "r"(a[2]), "r"(a[3]), "r"(b0), "r"(b1));
}
__device__ __forceinline__ void cp16(uint32_t dst, const void* src) {
    asm volatile("cp.async.cg.shared.global [%0], [%1], 16;"
                 :: "r"(dst), "l"(src) : "memory");
}
__device__ __forceinline__ void cp_commit() {
    asm volatile("cp.async.commit_group;" ::: "memory");
}
template<int N>
__device__ __forceinline__ void cp_wait() {
    asm volatile("cp.async.wait_group %0;" :: "n"(N) : "memory");
}
// fp32 pair -> packed bf16x2 hi + packed bf16x2 residual(lo)
__device__ __forceinline__ void cvt_pair(float x0, float x1,
                                         uint32_t& h, uint32_t& l) {
    __nv_bfloat162 hb = __floats2bfloat162_rn(x0, x1);
    h = *reinterpret_cast<uint32_t*>(&hb);
    float r0 = x0 - __bfloat162float(hb.x);
    float r1 = x1 - __bfloat162float(hb.y);
    __nv_bfloat162 lb = __floats2bfloat162_rn(r0, r1);
    l = *reinterpret_cast<uint32_t*>(&lb);
}

// ---------------------------------------------------------------------------
// One-shot fp32 -> bf16 hi/lo split
// ---------------------------------------------------------------------------
__global__ void cvt_split(const float* __restrict__ s, bf16* __restrict__ h,
                          bf16* __restrict__ lo, int n2)
{
    int i = blockIdx.x * blockDim.x + threadIdx.x;
    if (i < n2) {
        float2 v = ((const float2*)s)[i];
        uint32_t hh, ll;
        cvt_pair(v.x, v.y, hh, ll);
        ((uint32_t*)h)[i] = hh;
        ((uint32_t*)lo)[i] = ll;
    }
}

// ===========================================================================
// Tensor-core GEMM, 4-stage cp.async pipeline.
// C[m,n] = sum_k A[m,k]*W[n,k]; CTA tile 128x128, K-chunk 32.
// D += Ah*Wh + Ah*Wl + Al*Wh (3-term compensation).
// MODE 0: epilogue -> Q/K ([b][h][t][d], Q pre-scaled 1/8) + V^T ([b][h][d][t]).
// MODE 1: epilogue -> C fp32 [4096][1024].
// ===========================================================================
#define BK      32
#define NCH     (GK / BK)
#define RS      80                 // 32 bf16 = 64B + 16B pad
#define TILE_B  (128 * RS)         // 10240
#define BUF_B   (4 * TILE_B)       // 40960
#define STAGES  4
#define GEMM_SMEM (STAGES * BUF_B) // 163840

template<int MODE>
__global__ void __launch_bounds__(256) gemm_tc(const bf16* __restrict__ Ah,
                                               const bf16* __restrict__ Al,
                                               const bf16* __restrict__ Wh,
                                               const bf16* __restrict__ Wl,
                                               float* __restrict__ C)
{
    extern __shared__ char smc[];

    const int tid = threadIdx.x;
    const int wid = tid >> 5;
    const int l   = tid & 31;
    const int m0  = blockIdx.y * 128;
    const int n0  = blockIdx.x * 128;
    const int wm  = wid & 1;
    const int wn  = wid >> 1;

    // 8 cp.async slots/thread: f = tid + q*256; tile = f>>9 (Ah,Al,Wh,Wl)
    const bf16* src[8];
    uint32_t soff[8];
    {
        const bf16* tp[4] = {Ah, Al, Wh, Wl};
#pragma unroll
        for (int q = 0; q < 8; q++) {
            const int f = tid + q * 256;
            const int tile = f >> 9, g = f & 511;
            const int r = g >> 2, u = g & 3;
            const int row = ((tile < 2) ? m0 : n0) + r;
            src[q]  = tp[tile] + (size_t)row * GK + u * 8;
            soff[q] = (uint32_t)(tile * TILE_B + r * RS + u * 16);
        }
    }
    const uint32_t sb = smem_u32(smc);

    // Prologue: issue stages 0..2
#pragma unroll
    for (int s = 0; s < STAGES - 1; s++) {
        const uint32_t dst = sb + (uint32_t)s * BUF_B;
        const int k0 = s * BK;
#pragma unroll
        for (int q = 0; q < 8; q++) cp16(dst + soff[q], src[q] + k0);
        cp_commit();
    }

    float acc[4][4][4];
#pragma unroll
    for (int i = 0; i < 4; i++)
#pragma unroll
        for (int j = 0; j < 4; j++)
#pragma unroll
            for (int k = 0; k < 4; k++) acc[i][j][k] = 0.f;

    const int lrow = l & 15;
    const int lku  = l >> 4;

    for (int c = 0; c < NCH; c++) {
        cp_wait<STAGES - 2>();      // stage c landed
        __syncthreads();

        const uint32_t buf = sb + (uint32_t)(c % STAGES) * BUF_B;
#pragma unroll
        for (int s = 0; s < 2; s++) {
            uint32_t ah[4][4], al[4][4], bh[2][4], bl[2][4];
            const uint32_t kcol = (uint32_t)(16 * (2 * s + lku));
#pragma unroll
            for (int i = 0; i < 4; i++) {
                uint32_t addr = buf + (uint32_t)((wm * 64 + i * 16 + lrow) * RS) + kcol;
                ldm4(ah[i], addr);
                ldm4(al[i], addr + TILE_B);
            }
#pragma unroll
            for (int jp = 0; jp < 2; jp++) {
                uint32_t addr = buf + 2 * TILE_B
                              + (uint32_t)((wn * 32 + jp * 16 + lrow) * RS) + kcol;
                ldm4(bh[jp], addr);
                ldm4(bl[jp], addr + TILE_B);
            }
#pragma unroll
            for (int i = 0; i < 4; i++)
#pragma unroll
                for (int j = 0; j < 4; j++) {
                    const int jp = j >> 1, p = j & 1;
                    mma_bf16(acc[i][j], ah[i], bh[jp][p], bh[jp][p + 2]);
                    mma_bf16(acc[i][j], ah[i], bl[jp][p], bl[jp][p + 2]);
                    mma_bf16(acc[i][j], al[i], bh[jp][p], bh[jp][p + 2]);
                }
        }

        // Issue stage c+3 (overwrites chunk c-1's stage; safe: all threads
        // finished chunk c-1 before this iteration's __syncthreads)
        const int nc = c + STAGES - 1;
        if (nc < NCH) {
            const uint32_t dst = sb + (uint32_t)(nc % STAGES) * BUF_B;
            const int k0 = nc * BK;
#pragma unroll
            for (int q = 0; q < 8; q++) cp16(dst + soff[q], src[q] + k0);
        }
        cp_commit();
    }

    // Epilogue
#pragma unroll
    for (int i = 0; i < 4; i++) {
#pragma unroll
        for (int j = 0; j < 4; j++) {
            const int gm0 = m0 + wm * 64 + i * 16 + (l >> 2);
            const int gn  = n0 + wn * 32 + j * 8 + 2 * (l & 3);
#pragma unroll
            for (int half = 0; half < 2; half++) {
                const int gm = gm0 + half * 8;
                float vx = acc[i][j][half * 2], vy = acc[i][j][half * 2 + 1];
                if (MODE == 1) {
                    *(float2*)&C[(size_t)gm * Csz + gn] = make_float2(vx, vy);
                } else {
                    const int b = gm >> 11, t = gm & (Tsz - 1);
                    const int which = gn >> 10, cc = gn & (Csz - 1);
                    const int h = cc >> 6, d = cc & 63;
                    if (which == 0) { vx *= 0.125f; vy *= 0.125f; }  // 1/sqrt(D)
                    uint32_t hh, ll;
                    cvt_pair(vx, vy, hh, ll);
                    const size_t bh_ = (size_t)b * Hn + h;
                    if (which == 0) {
                        *(uint32_t*)&g_qh[(bh_ * Tsz + t) * Dh + d] = hh;
                        *(uint32_t*)&g_ql[(bh_ * Tsz + t) * Dh + d] = ll;
                    } else if (which == 1) {
                        *(uint32_t*)&g_kh[(bh_ * Tsz + t) * Dh + d] = hh;
                        *(uint32_t*)&g_kl[(bh_ * Tsz + t) * Dh + d] = ll;
                    } else {  // V transposed: [b][h][d][t]
                        __nv_bfloat162 hv = *reinterpret_cast<__nv_bfloat162*>(&hh);
                        __nv_bfloat162 lv = *reinterpret_cast<__nv_bfloat162*>(&ll);
                        g_vth[(bh_ * Dh + d)     * Tsz + t] = hv.x;
                        g_vth[(bh_ * Dh + d + 1) * Tsz + t] = hv.y;
                        g_vtl[(bh_ * Dh + d)     * Tsz + t] = lv.x;
                        g_vtl[(bh_ * Dh + d + 1) * Tsz + t] = lv.y;
                    }
                }
            }
        }
    }
}

// ===========================================================================
// Tensor-core causal flash attention, cp.async double-buffered K/V.
// CTA = 64 queries of one (b,h); 128 threads / 4 warps (warp = 16 query rows).
// S = QhKh+QhKl+QlKh, online softmax in frags, P repacked from S frags,
// O += PhVh+PlVh+PhVl vs smem V^T. Output bf16 hi/lo into g_y2h/g_y2l.
// ===========================================================================
#define ARS    144                 // 64 bf16 = 128B + 16B pad
#define AT_B   (64 * ARS)          // 9216
#define AQ_H   0
#define AQ_L   (AT_B)
#define ASTG0  (2 * AT_B)          // stage base
#define ASTG_B (4 * AT_B)          // K_H,K_L,V_H,V_L per stage = 36864
#define AK_H   0
#define AK_L   (AT_B)
#define AV_H   (2 * AT_B)
#define AV_L   (3 * AT_B)
#define ATTN_SMEM (ASTG0 + 2 * ASTG_B)   // 92160

__global__ void __launch_bounds__(128) attn_tc()
{
    extern __shared__ char sma[];
    const uint32_t sb = smem_u32(sma);

    const int qt  = (int)gridDim.x - 1 - (int)blockIdx.x;  // heavy tiles first
    const int h   = blockIdx.y;
    const int b   = blockIdx.z;
    const int tid = threadIdx.x;
    const int w   = tid >> 5;
    const int l   = tid & 31;
    const int lrow = l & 15;
    const int lku  = l >> 4;
    const int q0   = qt * 64;

    const size_t bh_  = (size_t)b * Hn + h;
    const bf16* qhG  = g_qh  + (bh_ * Tsz + q0) * Dh;
    const bf16* qlG  = g_ql  + (bh_ * Tsz + q0) * Dh;
    const bf16* khG  = g_kh  + bh_ * Tsz * Dh;
    const bf16* klG  = g_kl  + bh_ * Tsz * Dh;
    const bf16* vthG = g_vth + bh_ * Dh * Tsz;
    const bf16* vtlG = g_vtl + bh_ * Dh * Tsz;

    // Issue K/V tile jt into stage st (2048 cp16 slots over 128 threads)
    auto issue_tile = [&](int jt, int st) {
        const int kk0 = jt * 64;
        const uint32_t base = sb + ASTG0 + (uint32_t)st * ASTG_B;
#pragma unroll
        for (int q = 0; q < 16; q++) {
            const int idx = tid + q * 128;
            const int arr = idx >> 9, g = idx & 511;
            const int r = g >> 3, u = g & 7;
            const uint32_t dst = base + (uint32_t)(arr * AT_B + r * ARS + u * 16);
            const bf16* s;
            if      (arr == 0) s = khG  + (size_t)(kk0 + r) * Dh + u * 8;
            else if (arr == 1) s = klG  + (size_t)(kk0 + r) * Dh + u * 8;
            else if (arr == 2) s = vthG + (size_t)r * Tsz + kk0 + u * 8;
            else               s = vtlG + (size_t)r * Tsz + kk0 + u * 8;
            cp16(dst, s);
        }
        cp_commit();
    };

    issue_tile(0, 0);

    // Q tile -> smem -> register fragments
    for (int idx = tid; idx < 512; idx += 128) {
        const int r = idx >> 3, u = idx & 7;
        *(uint4*)(sma + AQ_H + r * ARS + u * 16) = *(const uint4*)(qhG + r * Dh + u * 8);
        *(uint4*)(sma + AQ_L + r * ARS + u * 16) = *(const uint4*)(qlG + r * Dh + u * 8);
    }
    __syncthreads();

    uint32_t qh[4][4], ql[4][4];
#pragma unroll
    for (int ks = 0; ks < 4; ks++) {
        const uint32_t addr = sb + (uint32_t)((16 * w + lrow) * ARS + ks * 32 + lku * 16);
        ldm4(qh[ks], addr + AQ_H);
        ldm4(ql[ks], addr + AQ_L);
    }

    float m0v = -1e30f, m1v = -1e30f, l0v = 0.f, l1v = 0.f;
    float o[8][4];
#pragma unroll
    for (int j = 0; j < 8; j++)
#pragma unroll
        for (int k = 0; k < 4; k++) o[j][k] = 0.f;

    for (int jt = 0; jt <= qt; jt++) {
        // Prefetch next tile (into the stage holding jt-1, already consumed)
        if (jt < qt) { issue_tile(jt + 1, (jt + 1) & 1); cp_wait<1>(); }
        else         { cp_wait<0>(); }
        __syncthreads();

        const uint32_t stg = sb + ASTG0 + (uint32_t)(jt & 1) * ASTG_B;

        // ---- S = Q K^T (hi/lo 3-term) ----
        float s[8][4];
#pragma unroll
        for (int j = 0; j < 8; j++)
#pragma unroll
            for (int k = 0; k < 4; k++) s[j][k] = 0.f;

#pragma unroll
        for (int ks = 0; ks < 4; ks++) {
            uint32_t kh[4][4], kl[4][4];
            const uint32_t kc = (uint32_t)(ks * 32 + lku * 16);
#pragma unroll
            for (int jp = 0; jp < 4; jp++) {
                const uint32_t addr = stg + (uint32_t)((16 * jp + lrow) * ARS) + kc;
                ldm4(kh[jp], addr + AK_H);
                ldm4(kl[jp], addr + AK_L);
            }
#pragma unroll
            for (int j = 0; j < 8; j++) {
                const int jp = j >> 1, p = j & 1;
                mma_bf16(s[j], qh[ks], kh[jp][p], kh[jp][p + 2]);
                mma_bf16(s[j], qh[ks], kl[jp][p], kl[jp][p + 2]);
                mma_bf16(s[j], ql[ks], kh[jp][p], kh[jp][p + 2]);
            }
        }

        // ---- Causal mask (diagonal tile only) ----
        if (jt == qt) {
            const int row0 = 16 * w + (l >> 2);
#pragma unroll
            for (int j = 0; j < 8; j++) {
                const int col = j * 8 + 2 * (l & 3);
                if (col     > row0)     s[j][0] = -1e30f;
                if (col + 1 > row0)     s[j][1] = -1e30f;
                if (col     > row0 + 8) s[j][2] = -1e30f;
                if (col + 1 > row0 + 8) s[j][3] = -1e30f;
            }
        }

        // ---- Online softmax (row = 4 consecutive lanes) ----
        float mx0 = -1e30f, mx1 = -1e30f;
#pragma unroll
        for (int j = 0; j < 8; j++) {
            mx0 = fmaxf(mx0, fmaxf(s[j][0], s[j][1]));
            mx1 = fmaxf(mx1, fmaxf(s[j][2], s[j][3]));
        }
        mx0 = fmaxf(mx0, __shfl_xor_sync(0xffffffffu, mx0, 1));
        mx0 = fmaxf(mx0, __shfl_xor_sync(0xffffffffu, mx0, 2));
        mx1 = fmaxf(mx1, __shfl_xor_sync(0xffffffffu, mx1, 1));
        mx1 = fmaxf(mx1, __shfl_xor_sync(0xffffffffu, mx1, 2));

        const float nm0 = fmaxf(m0v, mx0), nm1 = fmaxf(m1v, mx1);
        const float a0 = __expf(m0v - nm0), a1 = __expf(m1v - nm1);
        float rs0 = 0.f, rs1 = 0.f;
#pragma unroll
        for (int j = 0; j < 8; j++) {
            s[j][0] = __expf(s[j][0] - nm0); rs0 += s[j][0];
            s[j][1] = __expf(s[j][1] - nm0); rs0 += s[j][1];
            s[j][2] = __expf(s[j][2] - nm1); rs1 += s[j][2];
            s[j][3] = __expf(s[j][3] - nm1); rs1 += s[j][3];
        }
        rs0 += __shfl_xor_sync(0xffffffffu, rs0, 1);
        rs0 += __shfl_xor_sync(0xffffffffu, rs0, 2);
        rs1 += __shfl_xor_sync(0xffffffffu, rs1, 1);
        rs1 += __shfl_xor_sync(0xffffffffu, rs1, 2);
        l0v = l0v * a0 + rs0; m0v = nm0;
        l1v = l1v * a1 + rs1; m1v = nm1;
#pragma unroll
        for (int j = 0; j < 8; j++) {
            o[j][0] *= a0; o[j][1] *= a0;
            o[j][2] *= a1; o[j][3] *= a1;
        }

        // ---- P frags from S frags; O += P V ----
#pragma unroll
        for (int kt = 0; kt < 4; kt++) {
            uint32_t ph[4], pl[4];
            cvt_pair(s[2 * kt][0],     s[2 * kt][1],     ph[0], pl[0]);
            cvt_pair(s[2 * kt][2],     s[2 * kt][3],     ph[1], pl[1]);
            cvt_pair(s[2 * kt + 1][0], s[2 * kt + 1][1], ph[2], pl[2]);
            cvt_pair(s[2 * kt + 1][2], s[2 * kt + 1][3], ph[3], pl[3]);

            uint32_t vh[4][4], vl[4][4];
            const uint32_t kc = (uint32_t)(kt * 32 + lku * 16);
#pragma unroll
            for (int dp = 0; dp < 4; dp++) {
                const uint32_t addr = stg + (uint32_t)((16 * dp + lrow) * ARS) + kc;
                ldm4(vh[dp], addr + AV_H);
                ldm4(vl[dp], addr + AV_L);
            }
#pragma unroll
            for (int jd = 0; jd < 8; jd++) {
                const int dp = jd >> 1, p = jd & 1;
                mma_bf16(o[jd], ph, vh[dp][p], vh[dp][p + 2]);
                mma_bf16(o[jd], pl, vh[dp][p], vh[dp][p + 2]);
                mma_bf16(o[jd], ph, vl[dp][p], vl[dp][p + 2]);
            }
        }
        __syncthreads();   // all reads of this stage done before overwrite
    }

    // ---- Normalize + write y2 as bf16 hi/lo ----
    const float inv0 = 1.f / l0v, inv1 = 1.f / l1v;
    const int r0g = q0 + 16 * w + (l >> 2);
#pragma unroll
    for (int jd = 0; jd < 8; jd++) {
        const int col = h * Dh + jd * 8 + 2 * (l & 3);
        uint32_t hh, ll;
        cvt_pair(o[jd][0] * inv0, o[jd][1] * inv0, hh, ll);
        *(uint32_t*)&g_y2h[((size_t)b * Tsz + r0g) * Csz + col] = hh;
        *(uint32_t*)&g_y2l[((size_t)b * Tsz + r0g) * Csz + col] = ll;
        cvt_pair(o[jd][2] * inv1, o[jd][3] * inv1, hh, ll);
        *(uint32_t*)&g_y2h[((size_t)b * Tsz + r0g + 8) * Csz + col] = hh;
        *(uint32_t*)&g_y2l[((size_t)b * Tsz + r0g + 8) * Csz + col] = ll;
    }
}

// ===========================================================================
extern "C" void kernel_launch(void* const* d_in, const int* in_sizes, int n_in,
                              void* d_out, int out_size)
{
    const float* x      = (const float*)d_in[0];   // [B,T,C]
    const float* w_attn = (const float*)d_in[1];   // [3C,C]
    const float* w_proj = (const float*)d_in[2];   // [C,C]
    float* out = (float*)d_out;                    // [B,T,C]

    cudaFuncSetAttribute(gemm_tc<0>, cudaFuncAttributeMaxDynamicSharedMemorySize, GEMM_SMEM);
    cudaFuncSetAttribute(gemm_tc<1>, cudaFuncAttributeMaxDynamicSharedMemorySize, GEMM_SMEM);
    cudaFuncSetAttribute(attn_tc,    cudaFuncAttributeMaxDynamicSharedMemorySize, ATTN_SMEM);

    bf16 *xh, *xl, *wah, *wal, *wph, *wpl, *y2h, *y2l;
    cudaGetSymbolAddress((void**)&xh,  g_xh);  cudaGetSymbolAddress((void**)&xl,  g_xl);
    cudaGetSymbolAddress((void**)&wah, g_wah); cudaGetSymbolAddress((void**)&wal, g_wal);
    cudaGetSymbolAddress((void**)&wph, g_wph); cudaGetSymbolAddress((void**)&wpl, g_wpl);
    cudaGetSymbolAddress((void**)&y2h, g_y2h); cudaGetSymbolAddress((void**)&y2l, g_y2l);

    // 0) One-shot fp32 -> bf16 hi/lo splits
    {
        int n2;
        n2 = 4096 * 1024 / 2;
        cvt_split<<<(n2 + 255) / 256, 256>>>(x, xh, xl, n2);
        n2 = 3072 * 1024 / 2;
        cvt_split<<<(n2 + 255) / 256, 256>>>(w_attn, wah, wal, n2);
        n2 = 1024 * 1024 / 2;
        cvt_split<<<(n2 + 255) / 256, 256>>>(w_proj, wph, wpl, n2);
    }

    // 1) QKV projection -> Q/K ([b][h][t][d]) + V^T ([b][h][d][t]) bf16 h/l
    {
        dim3 grid((3 * Csz) / 128, (Bsz * Tsz) / 128);   // (24, 32)
        gemm_tc<0><<<grid, 256, GEMM_SMEM>>>(xh, xl, wah, wal, nullptr);
    }

    // 2) Tensor-core causal flash attention -> g_y2 (bf16 h/l)
    {
        dim3 grid(Tsz / 64, Hn, Bsz);                    // (32, 16, 2)
        attn_tc<<<grid, 128, ATTN_SMEM>>>();
    }

    // 3) Output projection -> d_out (fp32)
    {
        dim3 grid(Csz / 128, (Bsz * Tsz) / 128);         // (8, 32)
        gemm_tc<1><<<grid, 256, GEMM_SMEM>>>(y2h, y2l, wph, wpl, out);
    }
}

// round 12
// speedup vs baseline: 2.8861x; 1.1883x over previous
#include <cuda_runtime.h>
#include <cuda_bf16.h>
#include <cstdint>

// Problem constants
#define Bsz 2
#define Tsz 2048
#define Csz 1024
#define Hn  16
#define Dh  64
#define GK  1024

typedef __nv_bfloat16 bf16;

// ---------------------------------------------------------------------------
// Scratch (__device__ globals; no allocation allowed)
// ---------------------------------------------------------------------------
__device__ bf16 g_xh[(size_t)4096 * 1024], g_xl[(size_t)4096 * 1024];
__device__ bf16 g_wah[(size_t)3072 * 1024], g_wal[(size_t)3072 * 1024];
__device__ bf16 g_wph[(size_t)1024 * 1024], g_wpl[(size_t)1024 * 1024];
// Q,K: [b][h][t][d] ; V stored transposed: [b][h][d][t]
__device__ bf16 g_qh[(size_t)32 * 2048 * 64], g_ql[(size_t)32 * 2048 * 64];
__device__ bf16 g_kh[(size_t)32 * 2048 * 64], g_kl[(size_t)32 * 2048 * 64];
__device__ bf16 g_vth[(size_t)32 * 2048 * 64], g_vtl[(size_t)32 * 2048 * 64];
// attention output (pre-projection), bf16 hi/lo: [b*T][C]
__device__ bf16 g_y2h[(size_t)4096 * 1024], g_y2l[(size_t)4096 * 1024];

// ---------------------------------------------------------------------------
// Base-ISA helpers (compile clean for compute_103 base target)
// ---------------------------------------------------------------------------
__device__ __forceinline__ uint32_t smem_u32(const void* p) {
    uint32_t a;
    asm("{ .reg .u64 t; cvta.to.shared.u64 t, %1; cvt.u32.u64 %0, t; }"
        : "=r"(a) : "l"(p));
    return a;
}
__device__ __forceinline__ void ldm4(uint32_t* r, uint32_t addr) {
    asm volatile("ldmatrix.sync.aligned.m8n8.x4.shared.b16 {%0,%1,%2,%3}, [%4];"
                 : "=r"(r[0]), "=r"(r[1]), "=r"(r[2]), "=r"(r[3]) : "r"(addr));
}
__device__ __forceinline__ void mma_bf16(float* d, const uint32_t* a,
                                         uint32_t b0, uint32_t b1) {
    asm volatile(
        "mma.sync.aligned.m16n8k16.row.col.f32.bf16.bf16.f32 "
        "{%0,%1,%2,%3}, {%4,%5,%6,%7}, {%8,%9}, {%0,%1,%2,%3};"
        : "+f"(d[0]), "+f"(d[1]), "+f"(d[2]), "+f"(d[3])
        : "r"(a[0]), "r"(a[1]), "r"(a[2]), "r"(a[3]), "r"(b0), "r"(b1));
}
__device__ __forceinline__ void cp16(uint32_t dst, const void* src) {
    asm volatile("cp.async.cg.shared.global [%0], [%1], 16;"
                 :: "r"(dst), "l"(src) : "memory");
}
__device__ __forceinline__ void cp_commit() {
    asm volatile("cp.async.commit_group;" ::: "memory");
}
template<int N>
__device__ __forceinline__ void cp_wait() {
    asm volatile("cp.async.wait_group %0;" :: "n"(N) : "memory");
}
// fp32 pair -> packed bf16x2 hi + packed bf16x2 residual(lo)
__device__ __forceinline__ void cvt_pair(float x0, float x1,
                                         uint32_t& h, uint32_t& l) {
    __nv_bfloat162 hb = __floats2bfloat162_rn(x0, x1);
    h = *reinterpret_cast<uint32_t*>(&hb);
    float r0 = x0 - __bfloat162float(hb.x);
    float r1 = x1 - __bfloat162float(hb.y);
    __nv_bfloat162 lb = __floats2bfloat162_rn(r0, r1);
    l = *reinterpret_cast<uint32_t*>(&lb);
}

// ---------------------------------------------------------------------------
// One-shot fp32 -> bf16 hi/lo split
// ---------------------------------------------------------------------------
__global__ void cvt_split(const float* __restrict__ s, bf16* __restrict__ h,
                          bf16* __restrict__ lo, int n2)
{
    int i = blockIdx.x * blockDim.x + threadIdx.x;
    if (i < n2) {
        float2 v = ((const float2*)s)[i];
        uint32_t hh, ll;
        cvt_pair(v.x, v.y, hh, ll);
        ((uint32_t*)h)[i] = hh;
        ((uint32_t*)lo)[i] = ll;
    }
}

// ===========================================================================
// Tensor-core GEMM, 3-stage cp.async pipeline, swizzled 64B smem rows.
// C[m,n] = sum_k A[m,k]*W[n,k]; CTA tile 128x128, K-chunk 32.
// D += Ah*Wh + Ah*Wl + Al*Wh (3-term compensation).
// smem per CTA = 96KB -> 2 CTAs/SM (16 warps) for latency hiding.
// MODE 0: epilogue -> Q/K ([b][h][t][d], Q pre-scaled 1/8) + V^T ([b][h][d][t]).
// MODE 1: epilogue -> C fp32 [4096][1024].
// ===========================================================================
#define BK      32
#define NCH     (GK / BK)
#define TILE_B  (128 * 64)         // 8192: 128 rows x 64B (32 bf16), swizzled
#define BUF_B   (4 * TILE_B)       // 32768
#define STAGES  3
#define GEMM_SMEM (STAGES * BUF_B) // 98304

// Swizzled byte offset of 16B chunk (row r, chunk u in 0..3) within a tile.
__device__ __forceinline__ uint32_t swz(int r, int u) {
    return (uint32_t)(r * 64 + ((u ^ ((r >> 1) & 3)) * 16));
}

template<int MODE>
__global__ void __launch_bounds__(256, 2) gemm_tc(const bf16* __restrict__ Ah,
                                                  const bf16* __restrict__ Al,
                                                  const bf16* __restrict__ Wh,
                                                  const bf16* __restrict__ Wl,
                                                  float* __restrict__ C)
{
    extern __shared__ char smc[];

    const int tid = threadIdx.x;
    const int wid = tid >> 5;
    const int l   = tid & 31;
    const int m0  = blockIdx.y * 128;
    const int n0  = blockIdx.x * 128;
    const int wm  = wid & 1;
    const int wn  = wid >> 1;

    // 8 cp.async slots/thread: f = tid + q*256; tile = f>>9 (Ah,Al,Wh,Wl)
    const bf16* src[8];
    uint32_t soff[8];
    {
        const bf16* tp[4] = {Ah, Al, Wh, Wl};
#pragma unroll
        for (int q = 0; q < 8; q++) {
            const int f = tid + q * 256;
            const int tile = f >> 9, g = f & 511;
            const int r = g >> 2, u = g & 3;
            const int row = ((tile < 2) ? m0 : n0) + r;
            src[q]  = tp[tile] + (size_t)row * GK + u * 8;
            soff[q] = (uint32_t)(tile * TILE_B) + swz(r, u);
        }
    }
    const uint32_t sb = smem_u32(smc);

    // Prologue: issue stages 0..1
#pragma unroll
    for (int s = 0; s < STAGES - 1; s++) {
        const uint32_t dst = sb + (uint32_t)s * BUF_B;
        const int k0 = s * BK;
#pragma unroll
        for (int q = 0; q < 8; q++) cp16(dst + soff[q], src[q] + k0);
        cp_commit();
    }

    float acc[4][4][4];
#pragma unroll
    for (int i = 0; i < 4; i++)
#pragma unroll
        for (int j = 0; j < 4; j++)
#pragma unroll
            for (int k = 0; k < 4; k++) acc[i][j][k] = 0.f;

    const int lrow = l & 15;
    const int lku  = l >> 4;

    for (int c = 0; c < NCH; c++) {
        cp_wait<STAGES - 2>();      // stage c landed
        __syncthreads();

        const uint32_t buf = sb + (uint32_t)(c % STAGES) * BUF_B;
#pragma unroll
        for (int s = 0; s < 2; s++) {
            uint32_t ah[4][4], al[4][4], bh[2][4], bl[2][4];
            const int ku = 2 * s + lku;          // 16B chunk index 0..3
#pragma unroll
            for (int i = 0; i < 4; i++) {
                const int row = wm * 64 + i * 16 + lrow;
                uint32_t addr = buf + swz(row, ku);
                ldm4(ah[i], addr);
                ldm4(al[i], addr + TILE_B);
            }
#pragma unroll
            for (int jp = 0; jp < 2; jp++) {
                const int row = wn * 32 + jp * 16 + lrow;
                uint32_t addr = buf + 2 * TILE_B + swz(row, ku);
                ldm4(bh[jp], addr);
                ldm4(bl[jp], addr + TILE_B);
            }
#pragma unroll
            for (int i = 0; i < 4; i++)
#pragma unroll
                for (int j = 0; j < 4; j++) {
                    const int jp = j >> 1, p = j & 1;
                    mma_bf16(acc[i][j], ah[i], bh[jp][p], bh[jp][p + 2]);
                    mma_bf16(acc[i][j], ah[i], bl[jp][p], bl[jp][p + 2]);
                    mma_bf16(acc[i][j], al[i], bh[jp][p], bh[jp][p + 2]);
                }
        }

        // Issue stage c+2 into buffer (c+2)%3 == (c-1)%3, consumed at c-1;
        // all warps passed this iteration's barrier after finishing c-1.
        const int nc = c + STAGES - 1;
        if (nc < NCH) {
            const uint32_t dst = sb + (uint32_t)(nc % STAGES) * BUF_B;
            const int k0 = nc * BK;
#pragma unroll
            for (int q = 0; q < 8; q++) cp16(dst + soff[q], src[q] + k0);
        }
        cp_commit();
    }

    // Epilogue
#pragma unroll
    for (int i = 0; i < 4; i++) {
#pragma unroll
        for (int j = 0; j < 4; j++) {
            const int gm0 = m0 + wm * 64 + i * 16 + (l >> 2);
            const int gn  = n0 + wn * 32 + j * 8 + 2 * (l & 3);
#pragma unroll
            for (int half = 0; half < 2; half++) {
                const int gm = gm0 + half * 8;
                float vx = acc[i][j][half * 2], vy = acc[i][j][half * 2 + 1];
                if (MODE == 1) {
                    *(float2*)&C[(size_t)gm * Csz + gn] = make_float2(vx, vy);
                } else {
                    const int b = gm >> 11, t = gm & (Tsz - 1);
                    const int which = gn >> 10, cc = gn & (Csz - 1);
                    const int h = cc >> 6, d = cc & 63;
                    if (which == 0) { vx *= 0.125f; vy *= 0.125f; }  // 1/sqrt(D)
                    uint32_t hh, ll;
                    cvt_pair(vx, vy, hh, ll);
                    const size_t bh_ = (size_t)b * Hn + h;
                    if (which == 0) {
                        *(uint32_t*)&g_qh[(bh_ * Tsz + t) * Dh + d] = hh;
                        *(uint32_t*)&g_ql[(bh_ * Tsz + t) * Dh + d] = ll;
                    } else if (which == 1) {
                        *(uint32_t*)&g_kh[(bh_ * Tsz + t) * Dh + d] = hh;
                        *(uint32_t*)&g_kl[(bh_ * Tsz + t) * Dh + d] = ll;
                    } else {  // V transposed: [b][h][d][t]
                        __nv_bfloat162 hv = *reinterpret_cast<__nv_bfloat162*>(&hh);
                        __nv_bfloat162 lv = *reinterpret_cast<__nv_bfloat162*>(&ll);
                        g_vth[(bh_ * Dh + d)     * Tsz + t] = hv.x;
                        g_vth[(bh_ * Dh + d + 1) * Tsz + t] = hv.y;
                        g_vtl[(bh_ * Dh + d)     * Tsz + t] = lv.x;
                        g_vtl[(bh_ * Dh + d + 1) * Tsz + t] = lv.y;
                    }
                }
            }
        }
    }
}

// ===========================================================================
// Tensor-core causal flash attention, cp.async double-buffered K/V.
// CTA = 64 queries of one (b,h); 128 threads / 4 warps (warp = 16 query rows).
// S = QhKh+QhKl+QlKh, online softmax in frags, P repacked from S frags,
// O += PhVh+PlVh+PhVl vs smem V^T. Output bf16 hi/lo into g_y2h/g_y2l.
// ===========================================================================
#define ARS    144                 // 64 bf16 = 128B + 16B pad
#define AT_B   (64 * ARS)          // 9216
#define AQ_H   0
#define AQ_L   (AT_B)
#define ASTG0  (2 * AT_B)          // stage base
#define ASTG_B (4 * AT_B)          // K_H,K_L,V_H,V_L per stage = 36864
#define AK_H   0
#define AK_L   (AT_B)
#define AV_H   (2 * AT_B)
#define AV_L   (3 * AT_B)
#define ATTN_SMEM (ASTG0 + 2 * ASTG_B)   // 92160

__global__ void __launch_bounds__(128) attn_tc()
{
    extern __shared__ char sma[];
    const uint32_t sb = smem_u32(sma);

    const int qt  = (int)gridDim.x - 1 - (int)blockIdx.x;  // heavy tiles first
    const int h   = blockIdx.y;
    const int b   = blockIdx.z;
    const int tid = threadIdx.x;
    const int w   = tid >> 5;
    const int l   = tid & 31;
    const int lrow = l & 15;
    const int lku  = l >> 4;
    const int q0   = qt * 64;

    const size_t bh_  = (size_t)b * Hn + h;
    const bf16* qhG  = g_qh  + (bh_ * Tsz + q0) * Dh;
    const bf16* qlG  = g_ql  + (bh_ * Tsz + q0) * Dh;
    const bf16* khG  = g_kh  + bh_ * Tsz * Dh;
    const bf16* klG  = g_kl  + bh_ * Tsz * Dh;
    const bf16* vthG = g_vth + bh_ * Dh * Tsz;
    const bf16* vtlG = g_vtl + bh_ * Dh * Tsz;

    // Issue K/V tile jt into stage st (2048 cp16 slots over 128 threads)
    auto issue_tile = [&](int jt, int st) {
        const int kk0 = jt * 64;
        const uint32_t base = sb + ASTG0 + (uint32_t)st * ASTG_B;
#pragma unroll
        for (int q = 0; q < 16; q++) {
            const int idx = tid + q * 128;
            const int arr = idx >> 9, g = idx & 511;
            const int r = g >> 3, u = g & 7;
            const uint32_t dst = base + (uint32_t)(arr * AT_B + r * ARS + u * 16);
            const bf16* s;
            if      (arr == 0) s = khG  + (size_t)(kk0 + r) * Dh + u * 8;
            else if (arr == 1) s = klG  + (size_t)(kk0 + r) * Dh + u * 8;
            else if (arr == 2) s = vthG + (size_t)r * Tsz + kk0 + u * 8;
            else               s = vtlG + (size_t)r * Tsz + kk0 + u * 8;
            cp16(dst, s);
        }
        cp_commit();
    };

    issue_tile(0, 0);

    // Q tile -> smem -> register fragments
    for (int idx = tid; idx < 512; idx += 128) {
        const int r = idx >> 3, u = idx & 7;
        *(uint4*)(sma + AQ_H + r * ARS + u * 16) = *(const uint4*)(qhG + r * Dh + u * 8);
        *(uint4*)(sma + AQ_L + r * ARS + u * 16) = *(const uint4*)(qlG + r * Dh + u * 8);
    }
    __syncthreads();

    uint32_t qh[4][4], ql[4][4];
#pragma unroll
    for (int ks = 0; ks < 4; ks++) {
        const uint32_t addr = sb + (uint32_t)((16 * w + lrow) * ARS + ks * 32 + lku * 16);
        ldm4(qh[ks], addr + AQ_H);
        ldm4(ql[ks], addr + AQ_L);
    }

    float m0v = -1e30f, m1v = -1e30f, l0v = 0.f, l1v = 0.f;
    float o[8][4];
#pragma unroll
    for (int j = 0; j < 8; j++)
#pragma unroll
        for (int k = 0; k < 4; k++) o[j][k] = 0.f;

    for (int jt = 0; jt <= qt; jt++) {
        // Prefetch next tile (into the stage holding jt-1, already consumed)
        if (jt < qt) { issue_tile(jt + 1, (jt + 1) & 1); cp_wait<1>(); }
        else         { cp_wait<0>(); }
        __syncthreads();

        const uint32_t stg = sb + ASTG0 + (uint32_t)(jt & 1) * ASTG_B;

        // ---- S = Q K^T (hi/lo 3-term) ----
        float s[8][4];
#pragma unroll
        for (int j = 0; j < 8; j++)
#pragma unroll
            for (int k = 0; k < 4; k++) s[j][k] = 0.f;

#pragma unroll
        for (int ks = 0; ks < 4; ks++) {
            uint32_t kh[4][4], kl[4][4];
            const uint32_t kc = (uint32_t)(ks * 32 + lku * 16);
#pragma unroll
            for (int jp = 0; jp < 4; jp++) {
                const uint32_t addr = stg + (uint32_t)((16 * jp + lrow) * ARS) + kc;
                ldm4(kh[jp], addr + AK_H);
                ldm4(kl[jp], addr + AK_L);
            }
#pragma unroll
            for (int j = 0; j < 8; j++) {
                const int jp = j >> 1, p = j & 1;
                mma_bf16(s[j], qh[ks], kh[jp][p], kh[jp][p + 2]);
                mma_bf16(s[j], qh[ks], kl[jp][p], kl[jp][p + 2]);
                mma_bf16(s[j], ql[ks], kh[jp][p], kh[jp][p + 2]);
            }
        }

        // ---- Causal mask (diagonal tile only) ----
        if (jt == qt) {
            const int row0 = 16 * w + (l >> 2);
#pragma unroll
            for (int j = 0; j < 8; j++) {
                const int col = j * 8 + 2 * (l & 3);
                if (col     > row0)     s[j][0] = -1e30f;
                if (col + 1 > row0)     s[j][1] = -1e30f;
                if (col     > row0 + 8) s[j][2] = -1e30f;
                if (col + 1 > row0 + 8) s[j][3] = -1e30f;
            }
        }

        // ---- Online softmax (row = 4 consecutive lanes) ----
        float mx0 = -1e30f, mx1 = -1e30f;
#pragma unroll
        for (int j = 0; j < 8; j++) {
            mx0 = fmaxf(mx0, fmaxf(s[j][0], s[j][1]));
            mx1 = fmaxf(mx1, fmaxf(s[j][2], s[j][3]));
        }
        mx0 = fmaxf(mx0, __shfl_xor_sync(0xffffffffu, mx0, 1));
        mx0 = fmaxf(mx0, __shfl_xor_sync(0xffffffffu, mx0, 2));
        mx1 = fmaxf(mx1, __shfl_xor_sync(0xffffffffu, mx1, 1));
        mx1 = fmaxf(mx1, __shfl_xor_sync(0xffffffffu, mx1, 2));

        const float nm0 = fmaxf(m0v, mx0), nm1 = fmaxf(m1v, mx1);
        const float a0 = __expf(m0v - nm0), a1 = __expf(m1v - nm1);
        float rs0 = 0.f, rs1 = 0.f;
#pragma unroll
        for (int j = 0; j < 8; j++) {
            s[j][0] = __expf(s[j][0] - nm0); rs0 += s[j][0];
            s[j][1] = __expf(s[j][1] - nm0); rs0 += s[j][1];
            s[j][2] = __expf(s[j][2] - nm1); rs1 += s[j][2];
            s[j][3] = __expf(s[j][3] - nm1); rs1 += s[j][3];
        }
        rs0 += __shfl_xor_sync(0xffffffffu, rs0, 1);
        rs0 += __shfl_xor_sync(0xffffffffu, rs0, 2);
        rs1 += __shfl_xor_sync(0xffffffffu, rs1, 1);
        rs1 += __shfl_xor_sync(0xffffffffu, rs1, 2);
        l0v = l0v * a0 + rs0; m0v = nm0;
        l1v = l1v * a1 + rs1; m1v = nm1;
#pragma unroll
        for (int j = 0; j < 8; j++) {
            o[j][0] *= a0; o[j][1] *= a0;
            o[j][2] *= a1; o[j][3] *= a1;
        }

        // ---- P frags from S frags; O += P V ----
#pragma unroll
        for (int kt = 0; kt < 4; kt++) {
            uint32_t ph[4], pl[4];
            cvt_pair(s[2 * kt][0],     s[2 * kt][1],     ph[0], pl[0]);
            cvt_pair(s[2 * kt][2],     s[2 * kt][3],     ph[1], pl[1]);
            cvt_pair(s[2 * kt + 1][0], s[2 * kt + 1][1], ph[2], pl[2]);
            cvt_pair(s[2 * kt + 1][2], s[2 * kt + 1][3], ph[3], pl[3]);

            uint32_t vh[4][4], vl[4][4];
            const uint32_t kc = (uint32_t)(kt * 32 + lku * 16);
#pragma unroll
            for (int dp = 0; dp < 4; dp++) {
                const uint32_t addr = stg + (uint32_t)((16 * dp + lrow) * ARS) + kc;
                ldm4(vh[dp], addr + AV_H);
                ldm4(vl[dp], addr + AV_L);
            }
#pragma unroll
            for (int jd = 0; jd < 8; jd++) {
                const int dp = jd >> 1, p = jd & 1;
                mma_bf16(o[jd], ph, vh[dp][p], vh[dp][p + 2]);
                mma_bf16(o[jd], pl, vh[dp][p], vh[dp][p + 2]);
                mma_bf16(o[jd], ph, vl[dp][p], vl[dp][p + 2]);
            }
        }
        __syncthreads();   // all reads of this stage done before overwrite
    }

    // ---- Normalize + write y2 as bf16 hi/lo ----
    const float inv0 = 1.f / l0v, inv1 = 1.f / l1v;
    const int r0g = q0 + 16 * w + (l >> 2);
#pragma unroll
    for (int jd = 0; jd < 8; jd++) {
        const int col = h * Dh + jd * 8 + 2 * (l & 3);
        uint32_t hh, ll;
        cvt_pair(o[jd][0] * inv0, o[jd][1] * inv0, hh, ll);
        *(uint32_t*)&g_y2h[((size_t)b * Tsz + r0g) * Csz + col] = hh;
        *(uint32_t*)&g_y2l[((size_t)b * Tsz + r0g) * Csz + col] = ll;
        cvt_pair(o[jd][2] * inv1, o[jd][3] * inv1, hh, ll);
        *(uint32_t*)&g_y2h[((size_t)b * Tsz + r0g + 8) * Csz + col] = hh;
        *(uint32_t*)&g_y2l[((size_t)b * Tsz + r0g + 8) * Csz + col] = ll;
    }
}

// ===========================================================================
extern "C" void kernel_launch(void* const* d_in, const int* in_sizes, int n_in,
                              void* d_out, int out_size)
{
    const float* x      = (const float*)d_in[0];   // [B,T,C]
    const float* w_attn = (const float*)d_in[1];   // [3C,C]
    const float* w_proj = (const float*)d_in[2];   // [C,C]
    float* out = (float*)d_out;                    // [B,T,C]

    cudaFuncSetAttribute(gemm_tc<0>, cudaFuncAttributeMaxDynamicSharedMemorySize, GEMM_SMEM);
    cudaFuncSetAttribute(gemm_tc<1>, cudaFuncAttributeMaxDynamicSharedMemorySize, GEMM_SMEM);
    cudaFuncSetAttribute(attn_tc,    cudaFuncAttributeMaxDynamicSharedMemorySize, ATTN_SMEM);

    bf16 *xh, *xl, *wah, *wal, *wph, *wpl, *y2h, *y2l;
    cudaGetSymbolAddress((void**)&xh,  g_xh);  cudaGetSymbolAddress((void**)&xl,  g_xl);
    cudaGetSymbolAddress((void**)&wah, g_wah); cudaGetSymbolAddress((void**)&wal, g_wal);
    cudaGetSymbolAddress((void**)&wph, g_wph); cudaGetSymbolAddress((void**)&wpl, g_wpl);
    cudaGetSymbolAddress((void**)&y2h, g_y2h); cudaGetSymbolAddress((void**)&y2l, g_y2l);

    // 0) One-shot fp32 -> bf16 hi/lo splits
    {
        int n2;
        n2 = 4096 * 1024 / 2;
        cvt_split<<<(n2 + 255) / 256, 256>>>(x, xh, xl, n2);
        n2 = 3072 * 1024 / 2;
        cvt_split<<<(n2 + 255) / 256, 256>>>(w_attn, wah, wal, n2);
        n2 = 1024 * 1024 / 2;
        cvt_split<<<(n2 + 255) / 256, 256>>>(w_proj, wph, wpl, n2);
    }

    // 1) QKV projection -> Q/K ([b][h][t][d]) + V^T ([b][h][d][t]) bf16 h/l
    {
        dim3 grid((3 * Csz) / 128, (Bsz * Tsz) / 128);   // (24, 32)
        gemm_tc<0><<<grid, 256, GEMM_SMEM>>>(xh, xl, wah, wal, nullptr);
    }

    // 2) Tensor-core causal flash attention -> g_y2 (bf16 h/l)
    {
        dim3 grid(Tsz / 64, Hn, Bsz);                    // (32, 16, 2)
        attn_tc<<<grid, 128, ATTN_SMEM>>>();
    }

    // 3) Output projection -> d_out (fp32)
    {
        dim3 grid(Csz / 128, (Bsz * Tsz) / 128);         // (8, 32)
        gemm_tc<1><<<grid, 256, GEMM_SMEM>>>(y2h, y2l, wph, wpl, out);
    }
}

// round 13
// speedup vs baseline: 6.9184x; 2.3972x over previous
#include <cuda_runtime.h>
#include <cuda_fp16.h>
#include <cstdint>

// Problem constants
#define Bsz 2
#define Tsz 2048
#define Csz 1024
#define Hn  16
#define Dh  64
#define GK  1024

typedef __half h16;

// ---------------------------------------------------------------------------
// Scratch (__device__ globals; no allocation allowed)
// ---------------------------------------------------------------------------
__device__ h16 g_xh[(size_t)4096 * 1024];
__device__ h16 g_wah[(size_t)3072 * 1024];
__device__ h16 g_wph[(size_t)1024 * 1024];
// Q,K: [b][h][t][d] ; V stored transposed: [b][h][d][t]
__device__ h16 g_qh[(size_t)32 * 2048 * 64];
__device__ h16 g_kh[(size_t)32 * 2048 * 64];
__device__ h16 g_vth[(size_t)32 * 2048 * 64];
// attention output (pre-projection): [b*T][C]
__device__ h16 g_y2h[(size_t)4096 * 1024];

// ---------------------------------------------------------------------------
// Base-ISA helpers (compile clean for compute_103 base target)
// ---------------------------------------------------------------------------
__device__ __forceinline__ uint32_t smem_u32(const void* p) {
    uint32_t a;
    asm("{ .reg .u64 t; cvta.to.shared.u64 t, %1; cvt.u32.u64 %0, t; }"
        : "=r"(a) : "l"(p));
    return a;
}
__device__ __forceinline__ void ldm4(uint32_t* r, uint32_t addr) {
    asm volatile("ldmatrix.sync.aligned.m8n8.x4.shared.b16 {%0,%1,%2,%3}, [%4];"
                 : "=r"(r[0]), "=r"(r[1]), "=r"(r[2]), "=r"(r[3]) : "r"(addr));
}
__device__ __forceinline__ void mma_f16(float* d, const uint32_t* a,
                                        uint32_t b0, uint32_t b1) {
    asm volatile(
        "mma.sync.aligned.m16n8k16.row.col.f32.f16.f16.f32 "
        "{%0,%1,%2,%3}, {%4,%5,%6,%7}, {%8,%9}, {%0,%1,%2,%3};"
        : "+f"(d[0]), "+f"(d[1]), "+f"(d[2]), "+f"(d[3])
        : "r"(a[0]), "r"(a[1]), "r"(a[2]), "r"(a[3]), "r"(b0), "r"(b1));
}
__device__ __forceinline__ void cp16(uint32_t dst, const void* src) {
    asm volatile("cp.async.cg.shared.global [%0], [%1], 16;"
                 :: "r"(dst), "l"(src) : "memory");
}
__device__ __forceinline__ void cp_commit() {
    asm volatile("cp.async.commit_group;" ::: "memory");
}
template<int N>
__device__ __forceinline__ void cp_wait() {
    asm volatile("cp.async.wait_group %0;" :: "n"(N) : "memory");
}
__device__ __forceinline__ uint32_t pack_f16(float x0, float x1) {
    __half2 v = __floats2half2_rn(x0, x1);
    return *reinterpret_cast<uint32_t*>(&v);
}

// ---------------------------------------------------------------------------
// One-shot fp32 -> fp16 convert (grid-stride over float2)
// ---------------------------------------------------------------------------
__global__ void cvt_f16(const float* __restrict__ s, h16* __restrict__ h, int n2)
{
    int i = blockIdx.x * blockDim.x + threadIdx.x;
    if (i < n2) {
        float2 v = ((const float2*)s)[i];
        ((uint32_t*)h)[i] = pack_f16(v.x, v.y);
    }
}

// ===========================================================================
// Tensor-core GEMM (fp16 operands, fp32 accum), 4-stage cp.async pipeline,
// swizzled 64B smem rows. C[m,n] = sum_k A[m,k]*W[n,k]; CTA 128x128, BK=32.
// smem/CTA = 64KB -> 2 CTAs/SM.
// MODE 0: epilogue -> Q/K ([b][h][t][d], Q pre-scaled 1/8) + V^T ([b][h][d][t]).
// MODE 1: epilogue -> C fp32 [4096][1024].
// ===========================================================================
#define BK      32
#define NCH     (GK / BK)
#define TILE_B  (128 * 64)         // 8192: 128 rows x 64B (32 fp16), swizzled
#define BUF_B   (2 * TILE_B)       // 16384 (A, W)
#define STAGES  4
#define GEMM_SMEM (STAGES * BUF_B) // 65536

// Swizzled byte offset of 16B chunk (row r, chunk u in 0..3) within a tile.
__device__ __forceinline__ uint32_t swz(int r, int u) {
    return (uint32_t)(r * 64 + ((u ^ ((r >> 1) & 3)) * 16));
}

template<int MODE>
__global__ void __launch_bounds__(256, 2) gemm_tc(const h16* __restrict__ Ah,
                                                  const h16* __restrict__ Wh,
                                                  float* __restrict__ C)
{
    extern __shared__ char smc[];

    const int tid = threadIdx.x;
    const int wid = tid >> 5;
    const int l   = tid & 31;
    const int m0  = blockIdx.y * 128;
    const int n0  = blockIdx.x * 128;
    const int wm  = wid & 1;
    const int wn  = wid >> 1;

    // 4 cp.async slots/thread: f = tid + q*256; tile = f>>9 (A, W)
    const h16* src[4];
    uint32_t soff[4];
#pragma unroll
    for (int q = 0; q < 4; q++) {
        const int f = tid + q * 256;
        const int tile = f >> 9, g = f & 511;
        const int r = g >> 2, u = g & 3;
        const int row = (tile == 0 ? m0 : n0) + r;
        src[q]  = (tile == 0 ? Ah : Wh) + (size_t)row * GK + u * 8;
        soff[q] = (uint32_t)(tile * TILE_B) + swz(r, u);
    }
    const uint32_t sb = smem_u32(smc);

    // Prologue: issue stages 0..2
#pragma unroll
    for (int s = 0; s < STAGES - 1; s++) {
        const uint32_t dst = sb + (uint32_t)s * BUF_B;
        const int k0 = s * BK;
#pragma unroll
        for (int q = 0; q < 4; q++) cp16(dst + soff[q], src[q] + k0);
        cp_commit();
    }

    float acc[4][4][4];
#pragma unroll
    for (int i = 0; i < 4; i++)
#pragma unroll
        for (int j = 0; j < 4; j++)
#pragma unroll
            for (int k = 0; k < 4; k++) acc[i][j][k] = 0.f;

    const int lrow = l & 15;
    const int lku  = l >> 4;

    for (int c = 0; c < NCH; c++) {
        cp_wait<STAGES - 2>();      // stage c landed
        __syncthreads();

        const uint32_t buf = sb + (uint32_t)(c % STAGES) * BUF_B;
#pragma unroll
        for (int s = 0; s < 2; s++) {
            uint32_t ah[4][4], bh[2][4];
            const int ku = 2 * s + lku;          // 16B chunk index 0..3
#pragma unroll
            for (int i = 0; i < 4; i++) {
                const int row = wm * 64 + i * 16 + lrow;
                ldm4(ah[i], buf + swz(row, ku));
            }
#pragma unroll
            for (int jp = 0; jp < 2; jp++) {
                const int row = wn * 32 + jp * 16 + lrow;
                ldm4(bh[jp], buf + TILE_B + swz(row, ku));
            }
#pragma unroll
            for (int i = 0; i < 4; i++)
#pragma unroll
                for (int j = 0; j < 4; j++) {
                    const int jp = j >> 1, p = j & 1;
                    mma_f16(acc[i][j], ah[i], bh[jp][p], bh[jp][p + 2]);
                }
        }

        // Issue stage c+3 (that buffer was consumed at chunk c-1)
        const int nc = c + STAGES - 1;
        if (nc < NCH) {
            const uint32_t dst = sb + (uint32_t)(nc % STAGES) * BUF_B;
            const int k0 = nc * BK;
#pragma unroll
            for (int q = 0; q < 4; q++) cp16(dst + soff[q], src[q] + k0);
        }
        cp_commit();
    }

    // Epilogue
#pragma unroll
    for (int i = 0; i < 4; i++) {
#pragma unroll
        for (int j = 0; j < 4; j++) {
            const int gm0 = m0 + wm * 64 + i * 16 + (l >> 2);
            const int gn  = n0 + wn * 32 + j * 8 + 2 * (l & 3);
#pragma unroll
            for (int half = 0; half < 2; half++) {
                const int gm = gm0 + half * 8;
                float vx = acc[i][j][half * 2], vy = acc[i][j][half * 2 + 1];
                if (MODE == 1) {
                    *(float2*)&C[(size_t)gm * Csz + gn] = make_float2(vx, vy);
                } else {
                    const int b = gm >> 11, t = gm & (Tsz - 1);
                    const int which = gn >> 10, cc = gn & (Csz - 1);
                    const int h = cc >> 6, d = cc & 63;
                    if (which == 0) { vx *= 0.125f; vy *= 0.125f; }  // 1/sqrt(D)
                    const uint32_t hh = pack_f16(vx, vy);
                    const size_t bh_ = (size_t)b * Hn + h;
                    if (which == 0) {
                        *(uint32_t*)&g_qh[(bh_ * Tsz + t) * Dh + d] = hh;
                    } else if (which == 1) {
                        *(uint32_t*)&g_kh[(bh_ * Tsz + t) * Dh + d] = hh;
                    } else {  // V transposed: [b][h][d][t]
                        const __half2 hv = *reinterpret_cast<const __half2*>(&hh);
                        g_vth[(bh_ * Dh + d)     * Tsz + t] = __low2half(hv);
                        g_vth[(bh_ * Dh + d + 1) * Tsz + t] = __high2half(hv);
                    }
                }
            }
        }
    }
}

// ===========================================================================
// Tensor-core causal flash attention (fp16), cp.async double-buffered K/V.
// CTA = 64 queries of one (b,h); 128 threads / 4 warps (warp = 16 query rows).
// S = Q K^T, online softmax in frags, P repacked from S frags, O += P V
// vs smem V^T. Output fp16 into g_y2h. smem 45KB -> up to 4 CTAs/SM.
// ===========================================================================
#define ARS    144                 // 64 fp16 = 128B + 16B pad
#define AT_B   (64 * ARS)          // 9216
#define AQ_H   0
#define ASTG0  (AT_B)              // stage base
#define ASTG_B (2 * AT_B)          // K, V per stage = 18432
#define AK_H   0
#define AV_H   (AT_B)
#define ATTN_SMEM (ASTG0 + 2 * ASTG_B)   // 46080

__global__ void __launch_bounds__(128) attn_tc()
{
    extern __shared__ char sma[];
    const uint32_t sb = smem_u32(sma);

    const int qt  = (int)gridDim.x - 1 - (int)blockIdx.x;  // heavy tiles first
    const int h   = blockIdx.y;
    const int b   = blockIdx.z;
    const int tid = threadIdx.x;
    const int w   = tid >> 5;
    const int l   = tid & 31;
    const int lrow = l & 15;
    const int lku  = l >> 4;
    const int q0   = qt * 64;

    const size_t bh_  = (size_t)b * Hn + h;
    const h16* qhG  = g_qh  + (bh_ * Tsz + q0) * Dh;
    const h16* khG  = g_kh  + bh_ * Tsz * Dh;
    const h16* vthG = g_vth + bh_ * Dh * Tsz;

    // Issue K/V tile jt into stage st (1024 cp16 slots over 128 threads)
    auto issue_tile = [&](int jt, int st) {
        const int kk0 = jt * 64;
        const uint32_t base = sb + ASTG0 + (uint32_t)st * ASTG_B;
#pragma unroll
        for (int q = 0; q < 8; q++) {
            const int idx = tid + q * 128;
            const int arr = idx >> 9, g = idx & 511;
            const int r = g >> 3, u = g & 7;
            const uint32_t dst = base + (uint32_t)(arr * AT_B + r * ARS + u * 16);
            const h16* s = (arr == 0) ? (khG + (size_t)(kk0 + r) * Dh + u * 8)
                                      : (vthG + (size_t)r * Tsz + kk0 + u * 8);
            cp16(dst, s);
        }
        cp_commit();
    };

    issue_tile(0, 0);

    // Q tile -> smem -> register fragments
    for (int idx = tid; idx < 512; idx += 128) {
        const int r = idx >> 3, u = idx & 7;
        *(uint4*)(sma + AQ_H + r * ARS + u * 16) = *(const uint4*)(qhG + r * Dh + u * 8);
    }
    __syncthreads();

    uint32_t qh[4][4];
#pragma unroll
    for (int ks = 0; ks < 4; ks++) {
        const uint32_t addr = sb + (uint32_t)((16 * w + lrow) * ARS + ks * 32 + lku * 16);
        ldm4(qh[ks], addr + AQ_H);
    }

    float m0v = -1e30f, m1v = -1e30f, l0v = 0.f, l1v = 0.f;
    float o[8][4];
#pragma unroll
    for (int j = 0; j < 8; j++)
#pragma unroll
        for (int k = 0; k < 4; k++) o[j][k] = 0.f;

    for (int jt = 0; jt <= qt; jt++) {
        // Prefetch next tile (into the stage holding jt-1, already consumed)
        if (jt < qt) { issue_tile(jt + 1, (jt + 1) & 1); cp_wait<1>(); }
        else         { cp_wait<0>(); }
        __syncthreads();

        const uint32_t stg = sb + ASTG0 + (uint32_t)(jt & 1) * ASTG_B;

        // ---- S = Q K^T ----
        float s[8][4];
#pragma unroll
        for (int j = 0; j < 8; j++)
#pragma unroll
            for (int k = 0; k < 4; k++) s[j][k] = 0.f;

#pragma unroll
        for (int ks = 0; ks < 4; ks++) {
            uint32_t kh[4][4];
            const uint32_t kc = (uint32_t)(ks * 32 + lku * 16);
#pragma unroll
            for (int jp = 0; jp < 4; jp++) {
                ldm4(kh[jp], stg + AK_H + (uint32_t)((16 * jp + lrow) * ARS) + kc);
            }
#pragma unroll
            for (int j = 0; j < 8; j++) {
                const int jp = j >> 1, p = j & 1;
                mma_f16(s[j], qh[ks], kh[jp][p], kh[jp][p + 2]);
            }
        }

        // ---- Causal mask (diagonal tile only) ----
        if (jt == qt) {
            const int row0 = 16 * w + (l >> 2);
#pragma unroll
            for (int j = 0; j < 8; j++) {
                const int col = j * 8 + 2 * (l & 3);
                if (col     > row0)     s[j][0] = -1e30f;
                if (col + 1 > row0)     s[j][1] = -1e30f;
                if (col     > row0 + 8) s[j][2] = -1e30f;
                if (col + 1 > row0 + 8) s[j][3] = -1e30f;
            }
        }

        // ---- Online softmax (row = 4 consecutive lanes) ----
        float mx0 = -1e30f, mx1 = -1e30f;
#pragma unroll
        for (int j = 0; j < 8; j++) {
            mx0 = fmaxf(mx0, fmaxf(s[j][0], s[j][1]));
            mx1 = fmaxf(mx1, fmaxf(s[j][2], s[j][3]));
        }
        mx0 = fmaxf(mx0, __shfl_xor_sync(0xffffffffu, mx0, 1));
        mx0 = fmaxf(mx0, __shfl_xor_sync(0xffffffffu, mx0, 2));
        mx1 = fmaxf(mx1, __shfl_xor_sync(0xffffffffu, mx1, 1));
        mx1 = fmaxf(mx1, __shfl_xor_sync(0xffffffffu, mx1, 2));

        const float nm0 = fmaxf(m0v, mx0), nm1 = fmaxf(m1v, mx1);
        const float a0 = __expf(m0v - nm0), a1 = __expf(m1v - nm1);
        float rs0 = 0.f, rs1 = 0.f;
#pragma unroll
        for (int j = 0; j < 8; j++) {
            s[j][0] = __expf(s[j][0] - nm0); rs0 += s[j][0];
            s[j][1] = __expf(s[j][1] - nm0); rs0 += s[j][1];
            s[j][2] = __expf(s[j][2] - nm1); rs1 += s[j][2];
            s[j][3] = __expf(s[j][3] - nm1); rs1 += s[j][3];
        }
        rs0 += __shfl_xor_sync(0xffffffffu, rs0, 1);
        rs0 += __shfl_xor_sync(0xffffffffu, rs0, 2);
        rs1 += __shfl_xor_sync(0xffffffffu, rs1, 1);
        rs1 += __shfl_xor_sync(0xffffffffu, rs1, 2);
        l0v = l0v * a0 + rs0; m0v = nm0;
        l1v = l1v * a1 + rs1; m1v = nm1;
#pragma unroll
        for (int j = 0; j < 8; j++) {
            o[j][0] *= a0; o[j][1] *= a0;
            o[j][2] *= a1; o[j][3] *= a1;
        }

        // ---- P frags from S frags; O += P V ----
#pragma unroll
        for (int kt = 0; kt < 4; kt++) {
            uint32_t ph[4];
            ph[0] = pack_f16(s[2 * kt][0],     s[2 * kt][1]);
            ph[1] = pack_f16(s[2 * kt][2],     s[2 * kt][3]);
            ph[2] = pack_f16(s[2 * kt + 1][0], s[2 * kt + 1][1]);
            ph[3] = pack_f16(s[2 * kt + 1][2], s[2 * kt + 1][3]);

            uint32_t vh[4][4];
            const uint32_t kc = (uint32_t)(kt * 32 + lku * 16);
#pragma unroll
            for (int dp = 0; dp < 4; dp++) {
                ldm4(vh[dp], stg + AV_H + (uint32_t)((16 * dp + lrow) * ARS) + kc);
            }
#pragma unroll
            for (int jd = 0; jd < 8; jd++) {
                const int dp = jd >> 1, p = jd & 1;
                mma_f16(o[jd], ph, vh[dp][p], vh[dp][p + 2]);
            }
        }
        __syncthreads();   // all reads of this stage done before overwrite
    }

    // ---- Normalize + write y2 as fp16 ----
    const float inv0 = 1.f / l0v, inv1 = 1.f / l1v;
    const int r0g = q0 + 16 * w + (l >> 2);
#pragma unroll
    for (int jd = 0; jd < 8; jd++) {
        const int col = h * Dh + jd * 8 + 2 * (l & 3);
        *(uint32_t*)&g_y2h[((size_t)b * Tsz + r0g) * Csz + col] =
            pack_f16(o[jd][0] * inv0, o[jd][1] * inv0);
        *(uint32_t*)&g_y2h[((size_t)b * Tsz + r0g + 8) * Csz + col] =
            pack_f16(o[jd][2] * inv1, o[jd][3] * inv1);
    }
}

// ===========================================================================
extern "C" void kernel_launch(void* const* d_in, const int* in_sizes, int n_in,
                              void* d_out, int out_size)
{
    const float* x      = (const float*)d_in[0];   // [B,T,C]
    const float* w_attn = (const float*)d_in[1];   // [3C,C]
    const float* w_proj = (const float*)d_in[2];   // [C,C]
    float* out = (float*)d_out;                    // [B,T,C]

    cudaFuncSetAttribute(gemm_tc<0>, cudaFuncAttributeMaxDynamicSharedMemorySize, GEMM_SMEM);
    cudaFuncSetAttribute(gemm_tc<1>, cudaFuncAttributeMaxDynamicSharedMemorySize, GEMM_SMEM);
    cudaFuncSetAttribute(attn_tc,    cudaFuncAttributeMaxDynamicSharedMemorySize, ATTN_SMEM);

    h16 *xh, *wah, *wph, *y2h;
    cudaGetSymbolAddress((void**)&xh,  g_xh);
    cudaGetSymbolAddress((void**)&wah, g_wah);
    cudaGetSymbolAddress((void**)&wph, g_wph);
    cudaGetSymbolAddress((void**)&y2h, g_y2h);

    // 0) One-shot fp32 -> fp16 converts
    {
        int n2;
        n2 = 4096 * 1024 / 2;
        cvt_f16<<<(n2 + 255) / 256, 256>>>(x, xh, n2);
        n2 = 3072 * 1024 / 2;
        cvt_f16<<<(n2 + 255) / 256, 256>>>(w_attn, wah, n2);
        n2 = 1024 * 1024 / 2;
        cvt_f16<<<(n2 + 255) / 256, 256>>>(w_proj, wph, n2);
    }

    // 1) QKV projection -> Q/K ([b][h][t][d]) + V^T ([b][h][d][t]) fp16
    {
        dim3 grid((3 * Csz) / 128, (Bsz * Tsz) / 128);   // (24, 32)
        gemm_tc<0><<<grid, 256, GEMM_SMEM>>>(xh, wah, nullptr);
    }

    // 2) Tensor-core causal flash attention -> g_y2 (fp16)
    {
        dim3 grid(Tsz / 64, Hn, Bsz);                    // (32, 16, 2)
        attn_tc<<<grid, 128, ATTN_SMEM>>>();
    }

    // 3) Output projection -> d_out (fp32)
    {
        dim3 grid(Csz / 128, (Bsz * Tsz) / 128);         // (8, 32)
        gemm_tc<1><<<grid, 256, GEMM_SMEM>>>(y2h, wph, out);
    }
}

// round 14
// speedup vs baseline: 7.3218x; 1.0583x over previous
#include <cuda_runtime.h>
#include <cuda_fp16.h>
#include <cstdint>

// Problem constants
#define Bsz 2
#define Tsz 2048
#define Csz 1024
#define Hn  16
#define Dh  64
#define GK  1024

typedef __half h16;

// ---------------------------------------------------------------------------
// Scratch (__device__ globals; no allocation allowed)
// ---------------------------------------------------------------------------
__device__ h16 g_xh[(size_t)4096 * 1024];
__device__ h16 g_wah[(size_t)3072 * 1024];
__device__ h16 g_wph[(size_t)1024 * 1024];
// Q,K: [b][h][t][d] ; V stored transposed: [b][h][d][t]
__device__ h16 g_qh[(size_t)32 * 2048 * 64];
__device__ h16 g_kh[(size_t)32 * 2048 * 64];
__device__ h16 g_vth[(size_t)32 * 2048 * 64];
// attention output (pre-projection): [b*T][C]
__device__ h16 g_y2h[(size_t)4096 * 1024];

// ---------------------------------------------------------------------------
// Base-ISA helpers (compile clean for compute_103 base target)
// ---------------------------------------------------------------------------
__device__ __forceinline__ uint32_t smem_u32(const void* p) {
    uint32_t a;
    asm("{ .reg .u64 t; cvta.to.shared.u64 t, %1; cvt.u32.u64 %0, t; }"
        : "=r"(a) : "l"(p));
    return a;
}
__device__ __forceinline__ void ldm4(uint32_t* r, uint32_t addr) {
    asm volatile("ldmatrix.sync.aligned.m8n8.x4.shared.b16 {%0,%1,%2,%3}, [%4];"
                 : "=r"(r[0]), "=r"(r[1]), "=r"(r[2]), "=r"(r[3]) : "r"(addr));
}
__device__ __forceinline__ void mma_f16(float* d, const uint32_t* a,
                                        uint32_t b0, uint32_t b1) {
    asm volatile(
        "mma.sync.aligned.m16n8k16.row.col.f32.f16.f16.f32 "
        "{%0,%1,%2,%3}, {%4,%5,%6,%7}, {%8,%9}, {%0,%1,%2,%3};"
        : "+f"(d[0]), "+f"(d[1]), "+f"(d[2]), "+f"(d[3])
        : "r"(a[0]), "r"(a[1]), "r"(a[2]), "r"(a[3]), "r"(b0), "r"(b1));
}
__device__ __forceinline__ void cp16(uint32_t dst, const void* src) {
    asm volatile("cp.async.cg.shared.global [%0], [%1], 16;"
                 :: "r"(dst), "l"(src) : "memory");
}
__device__ __forceinline__ void cp_commit() {
    asm volatile("cp.async.commit_group;" ::: "memory");
}
template<int N>
__device__ __forceinline__ void cp_wait() {
    asm volatile("cp.async.wait_group %0;" :: "n"(N) : "memory");
}
__device__ __forceinline__ uint32_t pack_f16(float x0, float x1) {
    __half2 v = __floats2half2_rn(x0, x1);
    return *reinterpret_cast<uint32_t*>(&v);
}

// ---------------------------------------------------------------------------
// One-shot fp32 -> fp16 convert of all three inputs (single launch)
// ---------------------------------------------------------------------------
#define NX2  (4096 * 1024 / 2)
#define NWA2 (3072 * 1024 / 2)
#define NWP2 (1024 * 1024 / 2)

__global__ void cvt_all(const float* __restrict__ x,
                        const float* __restrict__ wa,
                        const float* __restrict__ wp)
{
    int i = blockIdx.x * blockDim.x + threadIdx.x;
    if (i < NX2) {
        float2 v = ((const float2*)x)[i];
        ((uint32_t*)g_xh)[i] = pack_f16(v.x, v.y);
    } else if (i < NX2 + NWA2) {
        const int j = i - NX2;
        float2 v = ((const float2*)wa)[j];
        ((uint32_t*)g_wah)[j] = pack_f16(v.x, v.y);
    } else {
        const int j = i - NX2 - NWA2;
        float2 v = ((const float2*)wp)[j];
        ((uint32_t*)g_wph)[j] = pack_f16(v.x, v.y);
    }
}

// ===========================================================================
// Tensor-core GEMM (fp16 operands, fp32 accum), 3-stage cp.async pipeline,
// 128B swizzled smem rows, BK=64. C[m,n] = sum_k A[m,k]*W[n,k]; CTA 128x128.
// smem/CTA = 96KB -> 2 CTAs/SM. 16 chunks -> half the barrier epochs of BK=32.
// MODE 0: epilogue -> Q/K ([b][h][t][d], Q pre-scaled 1/8) + V^T ([b][h][d][t]).
// MODE 1: epilogue -> C fp32 [4096][1024].
// ===========================================================================
#define BK      64
#define NCH     (GK / BK)          // 16
#define TILE_B  (128 * 128)        // 16384: 128 rows x 128B (64 fp16), swizzled
#define BUF_B   (2 * TILE_B)       // 32768 (A, W)
#define STAGES  3
#define GEMM_SMEM (STAGES * BUF_B) // 98304

// Swizzled byte offset of 16B chunk (row r, chunk u in 0..7) within a tile.
__device__ __forceinline__ uint32_t swz(int r, int u) {
    return (uint32_t)(r * 128 + ((u ^ (r & 7)) * 16));
}

template<int MODE>
__global__ void __launch_bounds__(256, 2) gemm_tc(const h16* __restrict__ Ah,
                                                  const h16* __restrict__ Wh,
                                                  float* __restrict__ C)
{
    extern __shared__ char smc[];

    const int tid = threadIdx.x;
    const int wid = tid >> 5;
    const int l   = tid & 31;
    const int m0  = blockIdx.y * 128;
    const int n0  = blockIdx.x * 128;
    const int wm  = wid & 1;
    const int wn  = wid >> 1;

    // 8 cp.async slots/thread: f = tid + q*256; tile = f>>10 (A, W)
    const h16* src[8];
    uint32_t soff[8];
#pragma unroll
    for (int q = 0; q < 8; q++) {
        const int f = tid + q * 256;
        const int tile = f >> 10, g = f & 1023;
        const int r = g >> 3, u = g & 7;
        const int row = (tile == 0 ? m0 : n0) + r;
        src[q]  = (tile == 0 ? Ah : Wh) + (size_t)row * GK + u * 8;
        soff[q] = (uint32_t)(tile * TILE_B) + swz(r, u);
    }
    const uint32_t sb = smem_u32(smc);

    // Prologue: issue stages 0..1
#pragma unroll
    for (int s = 0; s < STAGES - 1; s++) {
        const uint32_t dst = sb + (uint32_t)s * BUF_B;
        const int k0 = s * BK;
#pragma unroll
        for (int q = 0; q < 8; q++) cp16(dst + soff[q], src[q] + k0);
        cp_commit();
    }

    float acc[4][4][4];
#pragma unroll
    for (int i = 0; i < 4; i++)
#pragma unroll
        for (int j = 0; j < 4; j++)
#pragma unroll
            for (int k = 0; k < 4; k++) acc[i][j][k] = 0.f;

    const int lrow = l & 15;
    const int lku  = l >> 4;

    for (int c = 0; c < NCH; c++) {
        cp_wait<STAGES - 2>();      // stage c landed
        __syncthreads();

        const uint32_t buf = sb + (uint32_t)(c % STAGES) * BUF_B;
#pragma unroll
        for (int s = 0; s < 4; s++) {           // 4 k16 steps per 64-chunk
            uint32_t ah[4][4], bh[2][4];
            const int ku = 2 * s + lku;          // 16B chunk index 0..7
#pragma unroll
            for (int i = 0; i < 4; i++) {
                const int row = wm * 64 + i * 16 + lrow;
                ldm4(ah[i], buf + swz(row, ku));
            }
#pragma unroll
            for (int jp = 0; jp < 2; jp++) {
                const int row = wn * 32 + jp * 16 + lrow;
                ldm4(bh[jp], buf + TILE_B + swz(row, ku));
            }
#pragma unroll
            for (int i = 0; i < 4; i++)
#pragma unroll
                for (int j = 0; j < 4; j++) {
                    const int jp = j >> 1, p = j & 1;
                    mma_f16(acc[i][j], ah[i], bh[jp][p], bh[jp][p + 2]);
                }
        }

        // Issue stage c+2 into buffer (c+2)%3 == (c-1)%3 (consumed at c-1;
        // every warp passed this iteration's barrier only after finishing c-1)
        const int nc = c + STAGES - 1;
        if (nc < NCH) {
            const uint32_t dst = sb + (uint32_t)(nc % STAGES) * BUF_B;
            const int k0 = nc * BK;
#pragma unroll
            for (int q = 0; q < 8; q++) cp16(dst + soff[q], src[q] + k0);
        }
        cp_commit();
    }

    // Epilogue
#pragma unroll
    for (int i = 0; i < 4; i++) {
#pragma unroll
        for (int j = 0; j < 4; j++) {
            const int gm0 = m0 + wm * 64 + i * 16 + (l >> 2);
            const int gn  = n0 + wn * 32 + j * 8 + 2 * (l & 3);
#pragma unroll
            for (int half = 0; half < 2; half++) {
                const int gm = gm0 + half * 8;
                float vx = acc[i][j][half * 2], vy = acc[i][j][half * 2 + 1];
                if (MODE == 1) {
                    *(float2*)&C[(size_t)gm * Csz + gn] = make_float2(vx, vy);
                } else {
                    const int b = gm >> 11, t = gm & (Tsz - 1);
                    const int which = gn >> 10, cc = gn & (Csz - 1);
                    const int h = cc >> 6, d = cc & 63;
                    if (which == 0) { vx *= 0.125f; vy *= 0.125f; }  // 1/sqrt(D)
                    const uint32_t hh = pack_f16(vx, vy);
                    const size_t bh_ = (size_t)b * Hn + h;
                    if (which == 0) {
                        *(uint32_t*)&g_qh[(bh_ * Tsz + t) * Dh + d] = hh;
                    } else if (which == 1) {
                        *(uint32_t*)&g_kh[(bh_ * Tsz + t) * Dh + d] = hh;
                    } else {  // V transposed: [b][h][d][t]
                        const __half2 hv = *reinterpret_cast<const __half2*>(&hh);
                        g_vth[(bh_ * Dh + d)     * Tsz + t] = __low2half(hv);
                        g_vth[(bh_ * Dh + d + 1) * Tsz + t] = __high2half(hv);
                    }
                }
            }
        }
    }
}

// ===========================================================================
// Tensor-core causal flash attention (fp16), cp.async double-buffered K/V.
// CTA = 64 queries of one (b,h); 128 threads / 4 warps (warp = 16 query rows).
// S = Q K^T, online softmax in frags, P repacked from S frags, O += P V
// vs smem V^T. Output fp16 into g_y2h. smem 45KB -> up to 4 CTAs/SM.
// ===========================================================================
#define ARS    144                 // 64 fp16 = 128B + 16B pad
#define AT_B   (64 * ARS)          // 9216
#define AQ_H   0
#define ASTG0  (AT_B)              // stage base
#define ASTG_B (2 * AT_B)          // K, V per stage = 18432
#define AK_H   0
#define AV_H   (AT_B)
#define ATTN_SMEM (ASTG0 + 2 * ASTG_B)   // 46080

__global__ void __launch_bounds__(128) attn_tc()
{
    extern __shared__ char sma[];
    const uint32_t sb = smem_u32(sma);

    const int qt  = (int)gridDim.x - 1 - (int)blockIdx.x;  // heavy tiles first
    const int h   = blockIdx.y;
    const int b   = blockIdx.z;
    const int tid = threadIdx.x;
    const int w   = tid >> 5;
    const int l   = tid & 31;
    const int lrow = l & 15;
    const int lku  = l >> 4;
    const int q0   = qt * 64;

    const size_t bh_  = (size_t)b * Hn + h;
    const h16* qhG  = g_qh  + (bh_ * Tsz + q0) * Dh;
    const h16* khG  = g_kh  + bh_ * Tsz * Dh;
    const h16* vthG = g_vth + bh_ * Dh * Tsz;

    // Issue K/V tile jt into stage st (1024 cp16 slots over 128 threads)
    auto issue_tile = [&](int jt, int st) {
        const int kk0 = jt * 64;
        const uint32_t base = sb + ASTG0 + (uint32_t)st * ASTG_B;
#pragma unroll
        for (int q = 0; q < 8; q++) {
            const int idx = tid + q * 128;
            const int arr = idx >> 9, g = idx & 511;
            const int r = g >> 3, u = g & 7;
            const uint32_t dst = base + (uint32_t)(arr * AT_B + r * ARS + u * 16);
            const h16* s = (arr == 0) ? (khG + (size_t)(kk0 + r) * Dh + u * 8)
                                      : (vthG + (size_t)r * Tsz + kk0 + u * 8);
            cp16(dst, s);
        }
        cp_commit();
    };

    issue_tile(0, 0);

    // Q tile -> smem -> register fragments
    for (int idx = tid; idx < 512; idx += 128) {
        const int r = idx >> 3, u = idx & 7;
        *(uint4*)(sma + AQ_H + r * ARS + u * 16) = *(const uint4*)(qhG + r * Dh + u * 8);
    }
    __syncthreads();

    uint32_t qh[4][4];
#pragma unroll
    for (int ks = 0; ks < 4; ks++) {
        const uint32_t addr = sb + (uint32_t)((16 * w + lrow) * ARS + ks * 32 + lku * 16);
        ldm4(qh[ks], addr + AQ_H);
    }

    float m0v = -1e30f, m1v = -1e30f, l0v = 0.f, l1v = 0.f;
    float o[8][4];
#pragma unroll
    for (int j = 0; j < 8; j++)
#pragma unroll
        for (int k = 0; k < 4; k++) o[j][k] = 0.f;

    for (int jt = 0; jt <= qt; jt++) {
        // Prefetch next tile (into the stage holding jt-1, already consumed)
        if (jt < qt) { issue_tile(jt + 1, (jt + 1) & 1); cp_wait<1>(); }
        else         { cp_wait<0>(); }
        __syncthreads();

        const uint32_t stg = sb + ASTG0 + (uint32_t)(jt & 1) * ASTG_B;

        // ---- S = Q K^T ----
        float s[8][4];
#pragma unroll
        for (int j = 0; j < 8; j++)
#pragma unroll
            for (int k = 0; k < 4; k++) s[j][k] = 0.f;

#pragma unroll
        for (int ks = 0; ks < 4; ks++) {
            uint32_t kh[4][4];
            const uint32_t kc = (uint32_t)(ks * 32 + lku * 16);
#pragma unroll
            for (int jp = 0; jp < 4; jp++) {
                ldm4(kh[jp], stg + AK_H + (uint32_t)((16 * jp + lrow) * ARS) + kc);
            }
#pragma unroll
            for (int j = 0; j < 8; j++) {
                const int jp = j >> 1, p = j & 1;
                mma_f16(s[j], qh[ks], kh[jp][p], kh[jp][p + 2]);
            }
        }

        // ---- Causal mask (diagonal tile only) ----
        if (jt == qt) {
            const int row0 = 16 * w + (l >> 2);
#pragma unroll
            for (int j = 0; j < 8; j++) {
                const int col = j * 8 + 2 * (l & 3);
                if (col     > row0)     s[j][0] = -1e30f;
                if (col + 1 > row0)     s[j][1] = -1e30f;
                if (col     > row0 + 8) s[j][2] = -1e30f;
                if (col + 1 > row0 + 8) s[j][3] = -1e30f;
            }
        }

        // ---- Online softmax (row = 4 consecutive lanes) ----
        float mx0 = -1e30f, mx1 = -1e30f;
#pragma unroll
        for (int j = 0; j < 8; j++) {
            mx0 = fmaxf(mx0, fmaxf(s[j][0], s[j][1]));
            mx1 = fmaxf(mx1, fmaxf(s[j][2], s[j][3]));
        }
        mx0 = fmaxf(mx0, __shfl_xor_sync(0xffffffffu, mx0, 1));
        mx0 = fmaxf(mx0, __shfl_xor_sync(0xffffffffu, mx0, 2));
        mx1 = fmaxf(mx1, __shfl_xor_sync(0xffffffffu, mx1, 1));
        mx1 = fmaxf(mx1, __shfl_xor_sync(0xffffffffu, mx1, 2));

        const float nm0 = fmaxf(m0v, mx0), nm1 = fmaxf(m1v, mx1);
        const float a0 = __expf(m0v - nm0), a1 = __expf(m1v - nm1);
        float rs0 = 0.f, rs1 = 0.f;
#pragma unroll
        for (int j = 0; j < 8; j++) {
            s[j][0] = __expf(s[j][0] - nm0); rs0 += s[j][0];
            s[j][1] = __expf(s[j][1] - nm0); rs0 += s[j][1];
            s[j][2] = __expf(s[j][2] - nm1); rs1 += s[j][2];
            s[j][3] = __expf(s[j][3] - nm1); rs1 += s[j][3];
        }
        rs0 += __shfl_xor_sync(0xffffffffu, rs0, 1);
        rs0 += __shfl_xor_sync(0xffffffffu, rs0, 2);
        rs1 += __shfl_xor_sync(0xffffffffu, rs1, 1);
        rs1 += __shfl_xor_sync(0xffffffffu, rs1, 2);
        l0v = l0v * a0 + rs0; m0v = nm0;
        l1v = l1v * a1 + rs1; m1v = nm1;
#pragma unroll
        for (int j = 0; j < 8; j++) {
            o[j][0] *= a0; o[j][1] *= a0;
            o[j][2] *= a1; o[j][3] *= a1;
        }

        // ---- P frags from S frags; O += P V ----
#pragma unroll
        for (int kt = 0; kt < 4; kt++) {
            uint32_t ph[4];
            ph[0] = pack_f16(s[2 * kt][0],     s[2 * kt][1]);
            ph[1] = pack_f16(s[2 * kt][2],     s[2 * kt][3]);
            ph[2] = pack_f16(s[2 * kt + 1][0], s[2 * kt + 1][1]);
            ph[3] = pack_f16(s[2 * kt + 1][2], s[2 * kt + 1][3]);

            uint32_t vh[4][4];
            const uint32_t kc = (uint32_t)(kt * 32 + lku * 16);
#pragma unroll
            for (int dp = 0; dp < 4; dp++) {
                ldm4(vh[dp], stg + AV_H + (uint32_t)((16 * dp + lrow) * ARS) + kc);
            }
#pragma unroll
            for (int jd = 0; jd < 8; jd++) {
                const int dp = jd >> 1, p = jd & 1;
                mma_f16(o[jd], ph, vh[dp][p], vh[dp][p + 2]);
            }
        }
        __syncthreads();   // all reads of this stage done before overwrite
    }

    // ---- Normalize + write y2 as fp16 ----
    const float inv0 = 1.f / l0v, inv1 = 1.f / l1v;
    const int r0g = q0 + 16 * w + (l >> 2);
#pragma unroll
    for (int jd = 0; jd < 8; jd++) {
        const int col = h * Dh + jd * 8 + 2 * (l & 3);
        *(uint32_t*)&g_y2h[((size_t)b * Tsz + r0g) * Csz + col] =
            pack_f16(o[jd][0] * inv0, o[jd][1] * inv0);
        *(uint32_t*)&g_y2h[((size_t)b * Tsz + r0g + 8) * Csz + col] =
            pack_f16(o[jd][2] * inv1, o[jd][3] * inv1);
    }
}

// ===========================================================================
extern "C" void kernel_launch(void* const* d_in, const int* in_sizes, int n_in,
                              void* d_out, int out_size)
{
    const float* x      = (const float*)d_in[0];   // [B,T,C]
    const float* w_attn = (const float*)d_in[1];   // [3C,C]
    const float* w_proj = (const float*)d_in[2];   // [C,C]
    float* out = (float*)d_out;                    // [B,T,C]

    cudaFuncSetAttribute(gemm_tc<0>, cudaFuncAttributeMaxDynamicSharedMemorySize, GEMM_SMEM);
    cudaFuncSetAttribute(gemm_tc<1>, cudaFuncAttributeMaxDynamicSharedMemorySize, GEMM_SMEM);
    cudaFuncSetAttribute(attn_tc,    cudaFuncAttributeMaxDynamicSharedMemorySize, ATTN_SMEM);

    h16 *xh, *wah, *wph, *y2h;
    cudaGetSymbolAddress((void**)&xh,  g_xh);
    cudaGetSymbolAddress((void**)&wah, g_wah);
    cudaGetSymbolAddress((void**)&wph, g_wph);
    cudaGetSymbolAddress((void**)&y2h, g_y2h);

    // 0) One-shot fp32 -> fp16 converts (single launch)
    {
        const int total = NX2 + NWA2 + NWP2;
        cvt_all<<<(total + 255) / 256, 256>>>(x, w_attn, w_proj);
    }

    // 1) QKV projection -> Q/K ([b][h][t][d]) + V^T ([b][h][d][t]) fp16
    {
        dim3 grid((3 * Csz) / 128, (Bsz * Tsz) / 128);   // (24, 32)
        gemm_tc<0><<<grid, 256, GEMM_SMEM>>>(xh, wah, nullptr);
    }

    // 2) Tensor-core causal flash attention -> g_y2 (fp16)
    {
        dim3 grid(Tsz / 64, Hn, Bsz);                    // (32, 16, 2)
        attn_tc<<<grid, 128, ATTN_SMEM>>>();
    }

    // 3) Output projection -> d_out (fp32)
    {
        dim3 grid(Csz / 128, (Bsz * Tsz) / 128);         // (8, 32)
        gemm_tc<1><<<grid, 256, GEMM_SMEM>>>(y2h, wph, out);
    }
}